// round 1
// baseline (speedup 1.0000x reference)
#include <cuda_runtime.h>
#include <math.h>

// ---------------- problem constants ----------------
#define S_   256
#define B_   64
#define W_   16
#define Ec_  64
#define Hc_  128
#define E_   300
#define Hw_  512
#define T_   32
#define D_   557           // 1 + E + 2*Hc
#define NC_  (B_ * S_)     // 16384 words for char encoder

// ---------------- scratch (device globals; no allocs allowed) ----------------
__device__ float g_char_h[2][NC_ * Hc_];            // 2 x 8 MB
__device__ float g_char_c[2][NC_ * Hc_];
__device__ float g_char_gates[2][NC_ * 4 * Hc_];    // 2 x 32 MB
__device__ float g_x[S_ * B_ * D_];                 // 36.5 MB
__device__ float g_wxproj[2][S_ * B_ * 4 * Hw_];    // 2 x 134 MB
__device__ float g_word_h[2][B_ * Hw_];
__device__ float g_word_c[2][B_ * Hw_];
__device__ float g_word_gates[2][B_ * 4 * Hw_];
__device__ float g_enc[S_ * B_ * 2 * Hw_];          // 67 MB
__device__ float g_h1[S_ * B_ * Hw_];               // 33.5 MB
__device__ float g_logits[S_ * B_ * T_];            // 2 MB
__device__ float g_logZ[B_];

__device__ __forceinline__ float sigf(float x) { return 1.0f / (1.0f + expf(-x)); }

// ---------------- utility kernels ----------------
__global__ void zero_out_kernel(float* o, int n) {
    for (int i = blockIdx.x * blockDim.x + threadIdx.x; i < n; i += gridDim.x * blockDim.x)
        o[i] = 0.0f;
}

__global__ void zero_state_kernel() {
    int idx = blockIdx.x * blockDim.x + threadIdx.x;
    if (idx < 2 * NC_ * Hc_) {
        (&g_char_h[0][0])[idx] = 0.0f;
        (&g_char_c[0][0])[idx] = 0.0f;
    }
    if (idx < 2 * B_ * Hw_) {
        (&g_word_h[0][0])[idx] = 0.0f;
        (&g_word_c[0][0])[idx] = 0.0f;
    }
}

// ---------------- generic SGEMM: C = act(A @ Bw^T + bias1 + bias2) ----------------
// A: (M,K) row-major. Bw: (N,K) row-major (i.e. torch weight). C: (M,N).
template<int BM, int BN, int BK, int TM, int TN>
__global__ void __launch_bounds__((BM / TM) * (BN / TN))
sgemm(const float* __restrict__ A, const float* __restrict__ Bw,
      const float* __restrict__ bias1, const float* __restrict__ bias2,
      float* __restrict__ Cout, int M, int N, int K, int act)
{
    constexpr int THREADS = (BM / TM) * (BN / TN);
    __shared__ float As[BK][BM + 1];
    __shared__ float Bs[BK][BN + 1];
    const int m0 = blockIdx.y * BM;
    const int n0 = blockIdx.x * BN;
    const int tid = threadIdx.x;
    const int tcol = tid % (BN / TN);
    const int trow = tid / (BN / TN);

    float acc[TM][TN];
#pragma unroll
    for (int i = 0; i < TM; i++)
#pragma unroll
        for (int j = 0; j < TN; j++) acc[i][j] = 0.0f;

    for (int k0 = 0; k0 < K; k0 += BK) {
#pragma unroll 4
        for (int i = tid; i < BM * BK; i += THREADS) {
            int mm = i / BK, kk = i % BK;
            int m = m0 + mm, k = k0 + kk;
            As[kk][mm] = (m < M && k < K) ? A[(size_t)m * K + k] : 0.0f;
        }
#pragma unroll 4
        for (int i = tid; i < BN * BK; i += THREADS) {
            int nn = i / BK, kk = i % BK;
            int n = n0 + nn, k = k0 + kk;
            Bs[kk][nn] = (n < N && k < K) ? Bw[(size_t)n * K + k] : 0.0f;
        }
        __syncthreads();
#pragma unroll
        for (int kk = 0; kk < BK; kk++) {
            float ra[TM], rb[TN];
#pragma unroll
            for (int i = 0; i < TM; i++) ra[i] = As[kk][trow * TM + i];
#pragma unroll
            for (int j = 0; j < TN; j++) rb[j] = Bs[kk][tcol * TN + j];
#pragma unroll
            for (int i = 0; i < TM; i++)
#pragma unroll
                for (int j = 0; j < TN; j++) acc[i][j] = fmaf(ra[i], rb[j], acc[i][j]);
        }
        __syncthreads();
    }
#pragma unroll
    for (int i = 0; i < TM; i++) {
        int m = m0 + trow * TM + i;
        if (m >= M) continue;
#pragma unroll
        for (int j = 0; j < TN; j++) {
            int n = n0 + tcol * TN + j;
            if (n >= N) continue;
            float v = acc[i][j];
            if (bias1) v += bias1[n];
            if (bias2) v += bias2[n];
            if (act == 1) v = tanhf(v);
            Cout[(size_t)m * N + n] = v;
        }
    }
}

// ---------------- char LSTM step: gates = emb[idx]@Wih^T + h@Whh^T + bih + bhh ----------
// grid: (512/64, 16384/128, 2)   block: 256
__global__ void __launch_bounds__(256)
char_gates_kernel(const int* __restrict__ cin, int tstep,
                  const float* __restrict__ emb,
                  const float* __restrict__ Wih_f, const float* __restrict__ Whh_f,
                  const float* __restrict__ bih_f, const float* __restrict__ bhh_f,
                  const float* __restrict__ Wih_b, const float* __restrict__ Whh_b,
                  const float* __restrict__ bih_b, const float* __restrict__ bhh_b)
{
    constexpr int BM = 128, BN = 64, BK = 16, TM = 8, TN = 4, THREADS = 256;
    constexpr int KK = Ec_ + Hc_;  // 192
    const int dir = blockIdx.z;
    const int t_eff = dir ? (W_ - 1 - tstep) : tstep;
    const float* Wih = dir ? Wih_b : Wih_f;
    const float* Whh = dir ? Whh_b : Whh_f;
    const float* bih = dir ? bih_b : bih_f;
    const float* bhh = dir ? bhh_b : bhh_f;
    const float* h = g_char_h[dir];
    float* out = g_char_gates[dir];

    __shared__ float As[BK][BM + 1];
    __shared__ float Bs[BK][BN + 1];
    const int m0 = blockIdx.y * BM, n0 = blockIdx.x * BN;
    const int tid = threadIdx.x;
    const int tcol = tid % (BN / TN), trow = tid / (BN / TN);

    float acc[TM][TN];
#pragma unroll
    for (int i = 0; i < TM; i++)
#pragma unroll
        for (int j = 0; j < TN; j++) acc[i][j] = 0.0f;

    for (int k0 = 0; k0 < KK; k0 += BK) {
#pragma unroll 4
        for (int i = tid; i < BM * BK; i += THREADS) {
            int mm = i / BK, kk = i % BK;
            int m = m0 + mm, k = k0 + kk;
            float v;
            if (k < Ec_) {
                int cid = cin[m * W_ + t_eff];
                v = emb[(size_t)cid * Ec_ + k];
            } else {
                v = h[(size_t)m * Hc_ + (k - Ec_)];
            }
            As[kk][mm] = v;
        }
#pragma unroll 4
        for (int i = tid; i < BN * BK; i += THREADS) {
            int nn = i / BK, kk = i % BK;
            int j = n0 + nn, k = k0 + kk;
            Bs[kk][nn] = (k < Ec_) ? Wih[(size_t)j * Ec_ + k]
                                   : Whh[(size_t)j * Hc_ + (k - Ec_)];
        }
        __syncthreads();
#pragma unroll
        for (int kk = 0; kk < BK; kk++) {
            float ra[TM], rb[TN];
#pragma unroll
            for (int i = 0; i < TM; i++) ra[i] = As[kk][trow * TM + i];
#pragma unroll
            for (int j = 0; j < TN; j++) rb[j] = Bs[kk][tcol * TN + j];
#pragma unroll
            for (int i = 0; i < TM; i++)
#pragma unroll
                for (int j = 0; j < TN; j++) acc[i][j] = fmaf(ra[i], rb[j], acc[i][j]);
        }
        __syncthreads();
    }
#pragma unroll
    for (int i = 0; i < TM; i++) {
        int m = m0 + trow * TM + i;
#pragma unroll
        for (int j = 0; j < TN; j++) {
            int n = n0 + tcol * TN + j;
            out[(size_t)m * (4 * Hc_) + n] = acc[i][j] + bih[n] + bhh[n];
        }
    }
}

__global__ void __launch_bounds__(256)
char_cell_kernel()
{
    int idx = blockIdx.x * blockDim.x + threadIdx.x;
    if (idx >= 2 * NC_ * Hc_) return;
    int dir = idx / (NC_ * Hc_);
    int r = idx - dir * (NC_ * Hc_);
    int n = r / Hc_, j = r % Hc_;
    const float* gp = g_char_gates[dir] + (size_t)n * 4 * Hc_;
    float gi = gp[j], gf = gp[Hc_ + j], gg = gp[2 * Hc_ + j], go = gp[3 * Hc_ + j];
    float c = g_char_c[dir][r];
    c = sigf(gf) * c + sigf(gi) * tanhf(gg);
    g_char_c[dir][r] = c;
    g_char_h[dir][r] = sigf(go) * tanhf(c);
}

// ---------------- build word-LSTM input x = [we, cf, ce] ----------------
__global__ void __launch_bounds__(256)
build_x_kernel(const int* __restrict__ wid, const int* __restrict__ cap,
               const float* __restrict__ wemb, const float* __restrict__ cemb)
{
    int idx = blockIdx.x * blockDim.x + threadIdx.x;
    if (idx >= S_ * B_ * D_) return;
    int d = idx % D_;
    int sb = idx / D_;
    int s = sb / B_, b = sb % B_;
    float v;
    if (d < E_) {
        v = wemb[(size_t)wid[s * B_ + b] * E_ + d];
    } else if (d < E_ + 2 * Hc_) {
        int j = d - E_;
        int n = b * S_ + s;  // char encoder row = b*S + s
        v = (j < Hc_) ? g_char_h[0][(size_t)n * Hc_ + j]
                      : g_char_h[1][(size_t)n * Hc_ + (j - Hc_)];
    } else {
        v = cemb[cap[s * B_ + b]];
    }
    g_x[idx] = v;
}

// ---------------- word LSTM step: gates = xproj[s] + h@Whh^T  (both dirs via z) ------
// grid: (2048/64, 1, 2)  block: 256
__global__ void __launch_bounds__(256)
word_gates_kernel(const float* __restrict__ Whh_f, const float* __restrict__ Whh_b, int tstep)
{
    constexpr int BN = 64, BK = 16, TM = 4, TN = 4, THREADS = 256;
    constexpr int BM = 64;
    const int dir = blockIdx.z;
    const float* Whh = dir ? Whh_b : Whh_f;
    const float* h = g_word_h[dir];
    const int s = dir ? (S_ - 1 - tstep) : tstep;
    const float* src = g_wxproj[dir] + (size_t)s * B_ * 4 * Hw_;
    float* out = g_word_gates[dir];

    __shared__ float As[BK][BM + 1];
    __shared__ float Bs[BK][BN + 1];
    const int n0 = blockIdx.x * BN;
    const int tid = threadIdx.x;
    const int tcol = tid % (BN / TN), trow = tid / (BN / TN);

    float acc[TM][TN];
#pragma unroll
    for (int i = 0; i < TM; i++)
#pragma unroll
        for (int j = 0; j < TN; j++) acc[i][j] = 0.0f;

    for (int k0 = 0; k0 < Hw_; k0 += BK) {
#pragma unroll 4
        for (int i = tid; i < BM * BK; i += THREADS) {
            int mm = i / BK, kk = i % BK;
            As[kk][mm] = h[(size_t)mm * Hw_ + k0 + kk];
        }
#pragma unroll 4
        for (int i = tid; i < BN * BK; i += THREADS) {
            int nn = i / BK, kk = i % BK;
            Bs[kk][nn] = Whh[(size_t)(n0 + nn) * Hw_ + k0 + kk];
        }
        __syncthreads();
#pragma unroll
        for (int kk = 0; kk < BK; kk++) {
            float ra[TM], rb[TN];
#pragma unroll
            for (int i = 0; i < TM; i++) ra[i] = As[kk][trow * TM + i];
#pragma unroll
            for (int j = 0; j < TN; j++) rb[j] = Bs[kk][tcol * TN + j];
#pragma unroll
            for (int i = 0; i < TM; i++)
#pragma unroll
                for (int j = 0; j < TN; j++) acc[i][j] = fmaf(ra[i], rb[j], acc[i][j]);
        }
        __syncthreads();
    }
#pragma unroll
    for (int i = 0; i < TM; i++) {
        int m = trow * TM + i;
#pragma unroll
        for (int j = 0; j < TN; j++) {
            int n = n0 + tcol * TN + j;
            out[(size_t)m * (4 * Hw_) + n] = acc[i][j] + src[(size_t)m * (4 * Hw_) + n];
        }
    }
}

__global__ void __launch_bounds__(256)
word_cell_kernel(int tstep)
{
    int idx = blockIdx.x * blockDim.x + threadIdx.x;
    if (idx >= 2 * B_ * Hw_) return;
    int dir = idx / (B_ * Hw_);
    int r = idx - dir * (B_ * Hw_);
    int b = r / Hw_, j = r % Hw_;
    const float* gp = g_word_gates[dir] + (size_t)b * 4 * Hw_;
    float gi = gp[j], gf = gp[Hw_ + j], gg = gp[2 * Hw_ + j], go = gp[3 * Hw_ + j];
    float c = g_word_c[dir][r];
    c = sigf(gf) * c + sigf(gi) * tanhf(gg);
    g_word_c[dir][r] = c;
    float hv = sigf(go) * tanhf(c);
    g_word_h[dir][r] = hv;
    int s_out = dir ? (S_ - 1 - tstep) : tstep;
    g_enc[((size_t)s_out * B_ + b) * (2 * Hw_) + dir * Hw_ + j] = hv;
}

// ---------------- CRF forward (logZ per batch) ----------------
__global__ void __launch_bounds__(32)
crf_alpha_kernel(const float* __restrict__ trans, const float* __restrict__ start,
                 const float* __restrict__ endv)
{
    __shared__ float tr[T_][T_];
    __shared__ float alpha[T_];
    const int b = blockIdx.x;
    const int to = threadIdx.x;
    for (int i = to; i < T_ * T_; i += T_) tr[i / T_][i % T_] = trans[i];
    alpha[to] = start[to] + g_logits[(size_t)(0 * B_ + b) * T_ + to];
    __syncthreads();
    for (int s = 1; s < S_; s++) {
        float m = -1e30f;
#pragma unroll
        for (int f = 0; f < T_; f++) m = fmaxf(m, alpha[f] + tr[f][to]);
        float sum = 0.0f;
#pragma unroll
        for (int f = 0; f < T_; f++) sum += expf(alpha[f] + tr[f][to] - m);
        float a = m + logf(sum) + g_logits[((size_t)s * B_ + b) * T_ + to];
        __syncthreads();
        alpha[to] = a;
        __syncthreads();
    }
    float v = alpha[to] + endv[to];
    float m = v;
#pragma unroll
    for (int o = 16; o > 0; o >>= 1) m = fmaxf(m, __shfl_xor_sync(0xffffffffu, m, o));
    float e = expf(v - m);
#pragma unroll
    for (int o = 16; o > 0; o >>= 1) e += __shfl_xor_sync(0xffffffffu, e, o);
    if (to == 0) g_logZ[b] = m + logf(e);
}

// ---------------- CRF gold score + loss ----------------
__global__ void __launch_bounds__(64)
crf_loss_kernel(const int* __restrict__ tags, const float* __restrict__ trans,
                const float* __restrict__ start, const float* __restrict__ endv,
                float* __restrict__ out, int out_size)
{
    __shared__ float red[B_];
    const int b = threadIdx.x;
    int prev = tags[0 * B_ + b];
    float score = start[prev];
    for (int s = 0; s < S_; s++) {
        int tg = tags[s * B_ + b];
        score += g_logits[((size_t)s * B_ + b) * T_ + tg];
        if (s > 0) score += trans[prev * T_ + tg];
        prev = tg;
    }
    score += endv[prev];
    red[b] = g_logZ[b] - score;
    __syncthreads();
    if (b == 0) {
        float t = 0.0f;
        for (int i = 0; i < B_; i++) t += red[i];
        if (out_size > 0) out[0] = t;  // loss = -loglik
    }
}

// ---------------- Viterbi decode (forward + backtrace per batch block) ----------------
__global__ void __launch_bounds__(32)
viterbi_kernel(const float* __restrict__ trans, const float* __restrict__ start,
               const float* __restrict__ endv, float* __restrict__ out, int out_size)
{
    __shared__ float tr[T_][T_];
    __shared__ float v[T_];
    __shared__ unsigned char bp[S_ - 1][T_];
    const int b = blockIdx.x;
    const int to = threadIdx.x;
    for (int i = to; i < T_ * T_; i += T_) tr[i / T_][i % T_] = trans[i];
    v[to] = start[to] + g_logits[(size_t)b * T_ + to];
    __syncthreads();
    for (int s = 1; s < S_; s++) {
        float best = -1e30f;
        int arg = 0;
#pragma unroll
        for (int f = 0; f < T_; f++) {
            float sc = v[f] + tr[f][to];
            if (sc > best) { best = sc; arg = f; }
        }
        bp[s - 1][to] = (unsigned char)arg;
        float nv = best + g_logits[((size_t)s * B_ + b) * T_ + to];
        __syncthreads();
        v[to] = nv;
        __syncthreads();
    }
    if (to == 0) {
        float best = -1e30f;
        int last = 0;
        for (int f = 0; f < T_; f++) {
            float sc = v[f] + endv[f];
            if (sc > best) { best = sc; last = f; }
        }
        int tag = last;
        int base = 1 + b * S_;
        if (base + S_ - 1 < out_size) out[base + S_ - 1] = (float)tag;
        for (int s = S_ - 2; s >= 0; s--) {
            tag = bp[s][tag];
            if (base + s < out_size) out[base + s] = (float)tag;
        }
    }
}

// ---------------- host-side orchestration ----------------
extern "C" void kernel_launch(void* const* d_in, const int* in_sizes, int n_in,
                              void* d_out, int out_size) {
    (void)in_sizes; (void)n_in;
    const int*   word_inputs = (const int*)d_in[0];
    const int*   char_inputs = (const int*)d_in[1];
    const int*   cap_inputs  = (const int*)d_in[2];
    const int*   tag_inputs  = (const int*)d_in[3];
    const float* word_emb    = (const float*)d_in[4];
    const float* cap_emb     = (const float*)d_in[5];
    const float* char_emb    = (const float*)d_in[6];
    const float* cWih_f = (const float*)d_in[7];
    const float* cWhh_f = (const float*)d_in[8];
    const float* cbih_f = (const float*)d_in[9];
    const float* cbhh_f = (const float*)d_in[10];
    const float* cWih_b = (const float*)d_in[11];
    const float* cWhh_b = (const float*)d_in[12];
    const float* cbih_b = (const float*)d_in[13];
    const float* cbhh_b = (const float*)d_in[14];
    const float* wWih_f = (const float*)d_in[15];
    const float* wWhh_f = (const float*)d_in[16];
    const float* wbih_f = (const float*)d_in[17];
    const float* wbhh_f = (const float*)d_in[18];
    const float* wWih_b = (const float*)d_in[19];
    const float* wWhh_b = (const float*)d_in[20];
    const float* wbih_b = (const float*)d_in[21];
    const float* wbhh_b = (const float*)d_in[22];
    const float* ff1_W  = (const float*)d_in[23];
    const float* ff1_b  = (const float*)d_in[24];
    const float* ff2_W  = (const float*)d_in[25];
    const float* ff2_b  = (const float*)d_in[26];
    const float* trans  = (const float*)d_in[27];
    const float* start_trans = (const float*)d_in[28];
    const float* end_trans   = (const float*)d_in[29];
    float* out = (float*)d_out;

    // device-global scratch addresses (pure lookups; capture-safe)
    float *px = nullptr, *pwx = nullptr, *penc = nullptr, *ph1 = nullptr, *plog = nullptr;
    cudaGetSymbolAddress((void**)&px,   g_x);
    cudaGetSymbolAddress((void**)&pwx,  g_wxproj);
    cudaGetSymbolAddress((void**)&penc, g_enc);
    cudaGetSymbolAddress((void**)&ph1,  g_h1);
    cudaGetSymbolAddress((void**)&plog, g_logits);
    float* pwx0 = pwx;
    float* pwx1 = pwx + (size_t)S_ * B_ * 4 * Hw_;

    // 0) clear output + initial states
    zero_out_kernel<<<512, 256>>>(out, out_size);
    zero_state_kernel<<<(2 * NC_ * Hc_ + 255) / 256, 256>>>();

    // 1) char BiLSTM (both directions per launch)
    for (int t = 0; t < W_; t++) {
        char_gates_kernel<<<dim3(4 * Hc_ / 64, NC_ / 128, 2), 256>>>(
            char_inputs, t, char_emb,
            cWih_f, cWhh_f, cbih_f, cbhh_f,
            cWih_b, cWhh_b, cbih_b, cbhh_b);
        char_cell_kernel<<<(2 * NC_ * Hc_ + 255) / 256, 256>>>();
    }

    // 2) build word-LSTM input x = [we, cf, ce]
    build_x_kernel<<<(S_ * B_ * D_ + 255) / 256, 256>>>(word_inputs, cap_inputs, word_emb, cap_emb);

    // 3) word input projections (big GEMMs), bias folded in
    sgemm<128, 128, 16, 8, 8><<<dim3(4 * Hw_ / 128, S_ * B_ / 128), 256>>>(
        px, wWih_f, wbih_f, wbhh_f, pwx0, S_ * B_, 4 * Hw_, D_, 0);
    sgemm<128, 128, 16, 8, 8><<<dim3(4 * Hw_ / 128, S_ * B_ / 128), 256>>>(
        px, wWih_b, wbih_b, wbhh_b, pwx1, S_ * B_, 4 * Hw_, D_, 0);

    // 4) word BiLSTM recurrence (both directions per launch)
    for (int t = 0; t < S_; t++) {
        word_gates_kernel<<<dim3(4 * Hw_ / 64, 1, 2), 256>>>(wWhh_f, wWhh_b, t);
        word_cell_kernel<<<(2 * B_ * Hw_ + 255) / 256, 256>>>(t);
    }

    // 5) feed-forward head
    sgemm<128, 128, 16, 8, 8><<<dim3(Hw_ / 128, S_ * B_ / 128), 256>>>(
        penc, ff1_W, ff1_b, nullptr, ph1, S_ * B_, Hw_, 2 * Hw_, 1 /*tanh*/);
    sgemm<128, 32, 16, 4, 4><<<dim3(1, S_ * B_ / 128), 256>>>(
        ph1, ff2_W, ff2_b, nullptr, plog, S_ * B_, T_, Hw_, 0);

    // 6) CRF loss + Viterbi decode
    crf_alpha_kernel<<<B_, T_>>>(trans, start_trans, end_trans);
    crf_loss_kernel<<<1, B_>>>(tag_inputs, trans, start_trans, end_trans, out, out_size);
    viterbi_kernel<<<B_, T_>>>(trans, start_trans, end_trans, out, out_size);
}

// round 3
// speedup vs baseline: 1.5329x; 1.5329x over previous
#include <cuda_runtime.h>
#include <math.h>

// ---------------- problem constants ----------------
#define S_   256
#define B_   64
#define W_   16
#define Ec_  64
#define Hc_  128
#define E_   300
#define Hw_  512
#define T_   32
#define D_   557           // 1 + E + 2*Hc
#define Kp_  576           // D padded to multiple of 16
#define NC_  (B_ * S_)     // 16384 words for char encoder

// ---------------- scratch (device globals; no allocs allowed) ----------------
__device__ float g_char_h[2][2][NC_ * Hc_];         // [dir][buf]
__device__ float g_char_c[2][NC_ * Hc_];
__device__ float g_x[NC_ * Kp_];                    // padded input
__device__ float g_wWihp[2][4 * Hw_ * Kp_];         // padded word Wih
__device__ float g_wxproj[2][NC_ * 4 * Hw_];        // x@Wih^T + biases
__device__ float g_word_h[2][2][B_ * Hw_];
__device__ float g_word_c[2][B_ * Hw_];
__device__ float g_enc[NC_ * 2 * Hw_];
__device__ float g_h1[NC_ * Hw_];
__device__ float g_logits[NC_ * T_];
__device__ float g_logZ[B_];

__device__ __forceinline__ float sigf(float x) { return 1.0f / (1.0f + expf(-x)); }

__device__ __forceinline__ unsigned f2tf(float f) {
    unsigned u;
    asm("cvt.rna.tf32.f32 %0, %1;" : "=r"(u) : "f"(f));
    return u;
}
// fp32 -> (hi, lo) tf32 pair: v ~= hi + lo to ~21 mantissa bits
__device__ __forceinline__ void split_tf32(float v, unsigned& hi, unsigned& lo) {
    unsigned h = f2tf(v);
    float r = v - __uint_as_float(h);
    hi = h;
    lo = f2tf(r);
}

// one m16n8k8 tf32 mma, acc in-place
__device__ __forceinline__ void mma8(float* c, const unsigned* a, const unsigned* b) {
    asm volatile(
        "mma.sync.aligned.m16n8k8.row.col.f32.tf32.tf32.f32 "
        "{%0,%1,%2,%3}, {%4,%5,%6,%7}, {%8,%9}, {%0,%1,%2,%3};"
        : "+f"(c[0]), "+f"(c[1]), "+f"(c[2]), "+f"(c[3])
        : "r"(a[0]), "r"(a[1]), "r"(a[2]), "r"(a[3]), "r"(b[0]), "r"(b[1]));
}
// 3xTF32 emulated-fp32 mma
__device__ __forceinline__ void mma3(float* c, const unsigned* ah, const unsigned* al,
                                     const unsigned* bh, const unsigned* bl) {
    mma8(c, al, bh);
    mma8(c, ah, bl);
    mma8(c, ah, bh);
}

// ---------------- utility kernels ----------------
__global__ void zero_out_kernel(float* o, int n) {
    for (int i = blockIdx.x * blockDim.x + threadIdx.x; i < n; i += gridDim.x * blockDim.x)
        o[i] = 0.0f;
}

__global__ void zero_state_kernel() {
    int idx = blockIdx.x * blockDim.x + threadIdx.x;
    int n1 = 2 * 2 * NC_ * Hc_;
    int n2 = 2 * NC_ * Hc_;
    int n3 = 2 * 2 * B_ * Hw_;
    int n4 = 2 * B_ * Hw_;
    if (idx < n1) (&g_char_h[0][0][0])[idx] = 0.0f;
    if (idx < n2) (&g_char_c[0][0])[idx] = 0.0f;
    if (idx < n3) (&g_word_h[0][0][0])[idx] = 0.0f;
    if (idx < n4) (&g_word_c[0][0])[idx] = 0.0f;
}

__global__ void pad_wih_kernel(const float* __restrict__ Wf, const float* __restrict__ Wb) {
    int idx = blockIdx.x * blockDim.x + threadIdx.x;
    const int per = 4 * Hw_ * Kp_;
    if (idx >= 2 * per) return;
    int dir = idx / per;
    int r = idx - dir * per;
    int n = r / Kp_, k = r - n * Kp_;
    const float* Wsrc = dir ? Wb : Wf;
    g_wWihp[dir][r] = (k < D_) ? Wsrc[(size_t)n * D_ + k] : 0.0f;
}

// build padded word-LSTM input x = [we | cf | ce | 0pad], row = s*B+b, pitch Kp_
__global__ void __launch_bounds__(256)
build_x_kernel(const int* __restrict__ wid, const int* __restrict__ cap,
               const float* __restrict__ wemb, const float* __restrict__ cemb)
{
    int idx = blockIdx.x * blockDim.x + threadIdx.x;
    if (idx >= NC_ * Kp_) return;
    int d = idx % Kp_;
    int sb = idx / Kp_;
    int s = sb / B_, b = sb % B_;
    float v = 0.0f;
    if (d < E_) {
        v = wemb[(size_t)wid[s * B_ + b] * E_ + d];
    } else if (d < E_ + 2 * Hc_) {
        int j = d - E_;
        int n = b * S_ + s;  // char encoder row index
        v = (j < Hc_) ? g_char_h[0][0][(size_t)n * Hc_ + j]
                      : g_char_h[1][0][(size_t)n * Hc_ + (j - Hc_)];
    } else if (d == E_ + 2 * Hc_) {
        v = cemb[cap[s * B_ + b]];
    }
    g_x[idx] = v;
}

// ---------------- generic 3xTF32 GEMM: C = act(A @ W^T + b1 + b2) --------------
// A: (M,K) row-major, K%16==0, M%128==0. W: (N,K) row-major. C: (M,N).
// Block 256 thr, tile 128x128x16, warps 2x4, warp tile 64x32.
__global__ void __launch_bounds__(256)
mma_gemm(const float* __restrict__ A, const float* __restrict__ Wt,
         const float* __restrict__ b1, const float* __restrict__ b2,
         float* __restrict__ C, int M, int N, int K, int act)
{
    __shared__ float As[128][20];
    __shared__ float Ws[128][20];
    const int tid = threadIdx.x;
    const int w = tid >> 5, l = tid & 31;
    const int wm = w & 1, wn = w >> 1;
    const int g = l >> 2, tg = l & 3;
    const int m0 = blockIdx.y * 128, n0 = blockIdx.x * 128;

    float acc[4][4][4] = {};

    const int r = tid >> 2, c4 = (tid & 3) * 4;
    for (int k0 = 0; k0 < K; k0 += 16) {
#pragma unroll
        for (int h = 0; h < 2; h++) {
            int rr = r + h * 64;
            float4 va = *(const float4*)&A[(size_t)(m0 + rr) * K + k0 + c4];
            As[rr][c4 + 0] = va.x; As[rr][c4 + 1] = va.y;
            As[rr][c4 + 2] = va.z; As[rr][c4 + 3] = va.w;
            int n = n0 + rr;
            float4 vb = make_float4(0.f, 0.f, 0.f, 0.f);
            if (n < N) vb = *(const float4*)&Wt[(size_t)n * K + k0 + c4];
            Ws[rr][c4 + 0] = vb.x; Ws[rr][c4 + 1] = vb.y;
            Ws[rr][c4 + 2] = vb.z; Ws[rr][c4 + 3] = vb.w;
        }
        __syncthreads();
#pragma unroll
        for (int ks = 0; ks < 2; ks++) {
            unsigned ah[4][4], al[4][4], bh[4][2], bl[4][2];
#pragma unroll
            for (int mi = 0; mi < 4; mi++) {
                int rbase = wm * 64 + mi * 16 + g;
                split_tf32(As[rbase][ks * 8 + tg],         ah[mi][0], al[mi][0]);
                split_tf32(As[rbase + 8][ks * 8 + tg],     ah[mi][1], al[mi][1]);
                split_tf32(As[rbase][ks * 8 + tg + 4],     ah[mi][2], al[mi][2]);
                split_tf32(As[rbase + 8][ks * 8 + tg + 4], ah[mi][3], al[mi][3]);
            }
#pragma unroll
            for (int ni = 0; ni < 4; ni++) {
                int nb = wn * 32 + ni * 8 + g;
                split_tf32(Ws[nb][ks * 8 + tg],     bh[ni][0], bl[ni][0]);
                split_tf32(Ws[nb][ks * 8 + tg + 4], bh[ni][1], bl[ni][1]);
            }
#pragma unroll
            for (int mi = 0; mi < 4; mi++)
#pragma unroll
                for (int ni = 0; ni < 4; ni++)
                    mma3(acc[mi][ni], ah[mi], al[mi], bh[ni], bl[ni]);
        }
        __syncthreads();
    }
#pragma unroll
    for (int mi = 0; mi < 4; mi++) {
#pragma unroll
        for (int ni = 0; ni < 4; ni++) {
            int m = m0 + wm * 64 + mi * 16 + g;
            int n = n0 + wn * 32 + ni * 8 + 2 * tg;
#pragma unroll
            for (int q = 0; q < 4; q++) {
                int mm = m + (q >> 1) * 8;
                int nn = n + (q & 1);
                if (nn >= N) continue;
                float v = acc[mi][ni][q];
                if (b1) v += b1[nn];
                if (b2) v += b2[nn];
                if (act == 1) v = tanhf(v);
                C[(size_t)mm * N + nn] = v;
            }
        }
    }
}

// ---------------- fused char LSTM step (gates mma + cell) -----------------------
// grid: (Hc/32=4, NC/64=256, 2 dirs), block 256
// block tile: M=64 words, N=128 (4 gates x 32 j), K=192 = [emb(64) | h(128)]
__global__ void __launch_bounds__(256)
char_step_kernel(const int* __restrict__ cin, int t, const float* __restrict__ emb,
                 const float* __restrict__ Wih_f, const float* __restrict__ Whh_f,
                 const float* __restrict__ bih_f, const float* __restrict__ bhh_f,
                 const float* __restrict__ Wih_b, const float* __restrict__ Whh_b,
                 const float* __restrict__ bih_b, const float* __restrict__ bhh_b)
{
    const int dir = blockIdx.z;
    const int t_eff = dir ? (W_ - 1 - t) : t;
    const float* Wih = dir ? Wih_b : Wih_f;
    const float* Whh = dir ? Whh_b : Whh_f;
    const float* bih = dir ? bih_b : bih_f;
    const float* bhh = dir ? bhh_b : bhh_f;
    const float* hp = g_char_h[dir][t & 1];
    float* hn = g_char_h[dir][(t + 1) & 1];
    float* cst = g_char_c[dir];

    // smem union: [As 64x20 | Ws 128x20] overlaid later by zb 64x129
    __shared__ __align__(16) float sm[64 * 129];
    float (*As)[20] = (float(*)[20])sm;
    float (*Ws)[20] = (float(*)[20])(sm + 64 * 20);
    float (*zb)[129] = (float(*)[129])sm;

    const int tid = threadIdx.x;
    const int w = tid >> 5, l = tid & 31;
    const int wm = w & 1, wn = w >> 1;  // wn = gate
    const int g = l >> 2, tg = l & 3;
    const int j0 = blockIdx.x * 32;
    const int m0 = blockIdx.y * 64;

    float acc[2][4][4] = {};

    const int r = tid >> 2, c4 = (tid & 3) * 4;
#pragma unroll
    for (int kk = 0; kk < 12; kk++) {
        int k0 = kk * 16;
        // As: 64 rows x 16, 1 float4/thread
        {
            int m = m0 + r;
            int k = k0 + c4;
            float4 va;
            if (k < Ec_) {
                int cid = cin[m * W_ + t_eff];
                va = *(const float4*)&emb[(size_t)cid * Ec_ + k];
            } else {
                va = *(const float4*)&hp[(size_t)m * Hc_ + (k - Ec_)];
            }
            As[r][c4 + 0] = va.x; As[r][c4 + 1] = va.y;
            As[r][c4 + 2] = va.z; As[r][c4 + 3] = va.w;
        }
        // Ws: 128 rows x 16; row rr -> weight row (rr/32)*Hc + j0 + rr%32
#pragma unroll
        for (int h = 0; h < 2; h++) {
            int rr = r + h * 64;
            int wr = (rr >> 5) * Hc_ + j0 + (rr & 31);
            int k = k0 + c4;
            float4 vb;
            if (k < Ec_) vb = *(const float4*)&Wih[(size_t)wr * Ec_ + k];
            else         vb = *(const float4*)&Whh[(size_t)wr * Hc_ + (k - Ec_)];
            Ws[rr][c4 + 0] = vb.x; Ws[rr][c4 + 1] = vb.y;
            Ws[rr][c4 + 2] = vb.z; Ws[rr][c4 + 3] = vb.w;
        }
        __syncthreads();
#pragma unroll
        for (int ks = 0; ks < 2; ks++) {
            unsigned ah[2][4], al[2][4], bh[4][2], bl[4][2];
#pragma unroll
            for (int mi = 0; mi < 2; mi++) {
                int rbase = wm * 32 + mi * 16 + g;
                split_tf32(As[rbase][ks * 8 + tg],         ah[mi][0], al[mi][0]);
                split_tf32(As[rbase + 8][ks * 8 + tg],     ah[mi][1], al[mi][1]);
                split_tf32(As[rbase][ks * 8 + tg + 4],     ah[mi][2], al[mi][2]);
                split_tf32(As[rbase + 8][ks * 8 + tg + 4], ah[mi][3], al[mi][3]);
            }
#pragma unroll
            for (int ni = 0; ni < 4; ni++) {
                int nb = wn * 32 + ni * 8 + g;
                split_tf32(Ws[nb][ks * 8 + tg],     bh[ni][0], bl[ni][0]);
                split_tf32(Ws[nb][ks * 8 + tg + 4], bh[ni][1], bl[ni][1]);
            }
#pragma unroll
            for (int mi = 0; mi < 2; mi++)
#pragma unroll
                for (int ni = 0; ni < 4; ni++)
                    mma3(acc[mi][ni], ah[mi], al[mi], bh[ni], bl[ni]);
        }
        __syncthreads();
    }
    // stage z in smem (overlays As/Ws; all mma reads done past the sync above)
#pragma unroll
    for (int mi = 0; mi < 2; mi++) {
#pragma unroll
        for (int ni = 0; ni < 4; ni++) {
            int row = wm * 32 + mi * 16 + g;
            int col = wn * 32 + ni * 8 + 2 * tg;
            zb[row][col]         = acc[mi][ni][0];
            zb[row][col + 1]     = acc[mi][ni][1];
            zb[row + 8][col]     = acc[mi][ni][2];
            zb[row + 8][col + 1] = acc[mi][ni][3];
        }
    }
    __syncthreads();
    // cell update: 64 x 32 (m, j) pairs
    for (int idx = tid; idx < 64 * 32; idx += 256) {
        int ml = idx >> 5, jj = idx & 31;
        int j = j0 + jj;
        int m = m0 + ml;
        float zi = zb[ml][jj]      + bih[j]           + bhh[j];
        float zf = zb[ml][32 + jj] + bih[Hc_ + j]     + bhh[Hc_ + j];
        float zg = zb[ml][64 + jj] + bih[2 * Hc_ + j] + bhh[2 * Hc_ + j];
        float zo = zb[ml][96 + jj] + bih[3 * Hc_ + j] + bhh[3 * Hc_ + j];
        size_t off = (size_t)m * Hc_ + j;
        float c = cst[off];
        c = sigf(zf) * c + sigf(zi) * tanhf(zg);
        cst[off] = c;
        hn[off] = sigf(zo) * tanhf(c);
    }
}

// ---------------- fused word LSTM step (gates mma + cell) -----------------------
// grid: (Hw/16=32, 1, 2 dirs), block 256
// block tile: M=64 batch, N=64 (4 gates x 16 j), K=512
__global__ void __launch_bounds__(256)
word_step_kernel(const float* __restrict__ Whh_f, const float* __restrict__ Whh_b, int t)
{
    const int dir = blockIdx.z;
    const int s = dir ? (S_ - 1 - t) : t;
    const float* Whh = dir ? Whh_b : Whh_f;
    const float* hp = g_word_h[dir][t & 1];
    float* hn = g_word_h[dir][(t + 1) & 1];
    float* cst = g_word_c[dir];
    const float* xp = g_wxproj[dir] + (size_t)s * B_ * 4 * Hw_;

    __shared__ float As[64][20];
    __shared__ float Ws[64][20];
    __shared__ float zb[64][68];

    const int tid = threadIdx.x;
    const int w = tid >> 5, l = tid & 31;
    const int wm = w & 1, wn = w >> 1;  // wn = gate
    const int g = l >> 2, tg = l & 3;
    const int j0 = blockIdx.x * 16;

    float acc[2][2][4] = {};

    const int r = tid >> 2, c4 = (tid & 3) * 4;
#pragma unroll 4
    for (int kk = 0; kk < 32; kk++) {
        int k0 = kk * 16;
        {
            float4 va = *(const float4*)&hp[(size_t)r * Hw_ + k0 + c4];
            As[r][c4 + 0] = va.x; As[r][c4 + 1] = va.y;
            As[r][c4 + 2] = va.z; As[r][c4 + 3] = va.w;
            int wr = (r >> 4) * Hw_ + j0 + (r & 15);
            float4 vb = *(const float4*)&Whh[(size_t)wr * Hw_ + k0 + c4];
            Ws[r][c4 + 0] = vb.x; Ws[r][c4 + 1] = vb.y;
            Ws[r][c4 + 2] = vb.z; Ws[r][c4 + 3] = vb.w;
        }
        __syncthreads();
#pragma unroll
        for (int ks = 0; ks < 2; ks++) {
            unsigned ah[2][4], al[2][4], bh[2][2], bl[2][2];
#pragma unroll
            for (int mi = 0; mi < 2; mi++) {
                int rbase = wm * 32 + mi * 16 + g;
                split_tf32(As[rbase][ks * 8 + tg],         ah[mi][0], al[mi][0]);
                split_tf32(As[rbase + 8][ks * 8 + tg],     ah[mi][1], al[mi][1]);
                split_tf32(As[rbase][ks * 8 + tg + 4],     ah[mi][2], al[mi][2]);
                split_tf32(As[rbase + 8][ks * 8 + tg + 4], ah[mi][3], al[mi][3]);
            }
#pragma unroll
            for (int ni = 0; ni < 2; ni++) {
                int nb = wn * 16 + ni * 8 + g;
                split_tf32(Ws[nb][ks * 8 + tg],     bh[ni][0], bl[ni][0]);
                split_tf32(Ws[nb][ks * 8 + tg + 4], bh[ni][1], bl[ni][1]);
            }
#pragma unroll
            for (int mi = 0; mi < 2; mi++)
#pragma unroll
                for (int ni = 0; ni < 2; ni++)
                    mma3(acc[mi][ni], ah[mi], al[mi], bh[ni], bl[ni]);
        }
        __syncthreads();
    }
#pragma unroll
    for (int mi = 0; mi < 2; mi++) {
#pragma unroll
        for (int ni = 0; ni < 2; ni++) {
            int row = wm * 32 + mi * 16 + g;
            int col = wn * 16 + ni * 8 + 2 * tg;
            zb[row][col]         = acc[mi][ni][0];
            zb[row][col + 1]     = acc[mi][ni][1];
            zb[row + 8][col]     = acc[mi][ni][2];
            zb[row + 8][col + 1] = acc[mi][ni][3];
        }
    }
    __syncthreads();
    // cell: 64 x 16 (b, j) pairs
    for (int idx = tid; idx < 64 * 16; idx += 256) {
        int b = idx >> 4, jj = idx & 15;
        int j = j0 + jj;
        const float* xr = xp + (size_t)b * 4 * Hw_;
        float zi = zb[b][jj]      + xr[j];
        float zf = zb[b][16 + jj] + xr[Hw_ + j];
        float zg = zb[b][32 + jj] + xr[2 * Hw_ + j];
        float zo = zb[b][48 + jj] + xr[3 * Hw_ + j];
        size_t off = (size_t)b * Hw_ + j;
        float c = cst[off];
        c = sigf(zf) * c + sigf(zi) * tanhf(zg);
        cst[off] = c;
        float hv = sigf(zo) * tanhf(c);
        hn[off] = hv;
        g_enc[((size_t)s * B_ + b) * (2 * Hw_) + dir * Hw_ + j] = hv;
    }
}

// ---------------- CRF forward (logZ per batch) ----------------
__global__ void __launch_bounds__(32)
crf_alpha_kernel(const float* __restrict__ trans, const float* __restrict__ start,
                 const float* __restrict__ endv)
{
    __shared__ float tr[T_][T_];
    __shared__ float alpha[T_];
    const int b = blockIdx.x;
    const int to = threadIdx.x;
    for (int i = to; i < T_ * T_; i += T_) tr[i / T_][i % T_] = trans[i];
    alpha[to] = start[to] + g_logits[(size_t)(0 * B_ + b) * T_ + to];
    __syncthreads();
    for (int s = 1; s < S_; s++) {
        float m = -1e30f;
#pragma unroll
        for (int f = 0; f < T_; f++) m = fmaxf(m, alpha[f] + tr[f][to]);
        float sum = 0.0f;
#pragma unroll
        for (int f = 0; f < T_; f++) sum += expf(alpha[f] + tr[f][to] - m);
        float a = m + logf(sum) + g_logits[((size_t)s * B_ + b) * T_ + to];
        __syncthreads();
        alpha[to] = a;
        __syncthreads();
    }
    float v = alpha[to] + endv[to];
    float m = v;
#pragma unroll
    for (int o = 16; o > 0; o >>= 1) m = fmaxf(m, __shfl_xor_sync(0xffffffffu, m, o));
    float e = expf(v - m);
#pragma unroll
    for (int o = 16; o > 0; o >>= 1) e += __shfl_xor_sync(0xffffffffu, e, o);
    if (to == 0) g_logZ[b] = m + logf(e);
}

// ---------------- CRF gold score + loss ----------------
__global__ void __launch_bounds__(64)
crf_loss_kernel(const int* __restrict__ tags, const float* __restrict__ trans,
                const float* __restrict__ start, const float* __restrict__ endv,
                float* __restrict__ out, int out_size)
{
    __shared__ float red[B_];
    const int b = threadIdx.x;
    int prev = tags[0 * B_ + b];
    float score = start[prev];
    for (int s = 0; s < S_; s++) {
        int tg = tags[s * B_ + b];
        score += g_logits[((size_t)s * B_ + b) * T_ + tg];
        if (s > 0) score += trans[prev * T_ + tg];
        prev = tg;
    }
    score += endv[prev];
    red[b] = g_logZ[b] - score;
    __syncthreads();
    if (b == 0) {
        float t = 0.0f;
        for (int i = 0; i < B_; i++) t += red[i];
        if (out_size > 0) out[0] = t;
    }
}

// ---------------- Viterbi decode ----------------
__global__ void __launch_bounds__(32)
viterbi_kernel(const float* __restrict__ trans, const float* __restrict__ start,
               const float* __restrict__ endv, float* __restrict__ out, int out_size)
{
    __shared__ float tr[T_][T_];
    __shared__ float v[T_];
    __shared__ unsigned char bp[S_ - 1][T_];
    const int b = blockIdx.x;
    const int to = threadIdx.x;
    for (int i = to; i < T_ * T_; i += T_) tr[i / T_][i % T_] = trans[i];
    v[to] = start[to] + g_logits[(size_t)b * T_ + to];
    __syncthreads();
    for (int s = 1; s < S_; s++) {
        float best = -1e30f;
        int arg = 0;
#pragma unroll
        for (int f = 0; f < T_; f++) {
            float sc = v[f] + tr[f][to];
            if (sc > best) { best = sc; arg = f; }
        }
        bp[s - 1][to] = (unsigned char)arg;
        float nv = best + g_logits[((size_t)s * B_ + b) * T_ + to];
        __syncthreads();
        v[to] = nv;
        __syncthreads();
    }
    if (to == 0) {
        float best = -1e30f;
        int last = 0;
        for (int f = 0; f < T_; f++) {
            float sc = v[f] + endv[f];
            if (sc > best) { best = sc; last = f; }
        }
        int tag = last;
        int base = 1 + b * S_;
        if (base + S_ - 1 < out_size) out[base + S_ - 1] = (float)tag;
        for (int s = S_ - 2; s >= 0; s--) {
            tag = bp[s][tag];
            if (base + s < out_size) out[base + s] = (float)tag;
        }
    }
}

// ---------------- host-side orchestration ----------------
extern "C" void kernel_launch(void* const* d_in, const int* in_sizes, int n_in,
                              void* d_out, int out_size) {
    (void)in_sizes; (void)n_in;
    const int*   word_inputs = (const int*)d_in[0];
    const int*   char_inputs = (const int*)d_in[1];
    const int*   cap_inputs  = (const int*)d_in[2];
    const int*   tag_inputs  = (const int*)d_in[3];
    const float* word_emb    = (const float*)d_in[4];
    const float* cap_emb     = (const float*)d_in[5];
    const float* char_emb    = (const float*)d_in[6];
    const float* cWih_f = (const float*)d_in[7];
    const float* cWhh_f = (const float*)d_in[8];
    const float* cbih_f = (const float*)d_in[9];
    const float* cbhh_f = (const float*)d_in[10];
    const float* cWih_b = (const float*)d_in[11];
    const float* cWhh_b = (const float*)d_in[12];
    const float* cbih_b = (const float*)d_in[13];
    const float* cbhh_b = (const float*)d_in[14];
    const float* wWih_f = (const float*)d_in[15];
    const float* wWhh_f = (const float*)d_in[16];
    const float* wbih_f = (const float*)d_in[17];
    const float* wbhh_f = (const float*)d_in[18];
    const float* wWih_b = (const float*)d_in[19];
    const float* wWhh_b = (const float*)d_in[20];
    const float* wbih_b = (const float*)d_in[21];
    const float* wbhh_b = (const float*)d_in[22];
    const float* ff1_W  = (const float*)d_in[23];
    const float* ff1_b  = (const float*)d_in[24];
    const float* ff2_W  = (const float*)d_in[25];
    const float* ff2_b  = (const float*)d_in[26];
    const float* trans  = (const float*)d_in[27];
    const float* start_trans = (const float*)d_in[28];
    const float* end_trans   = (const float*)d_in[29];
    float* out = (float*)d_out;

    float *px = nullptr, *pwihp = nullptr, *pwx = nullptr, *penc = nullptr,
          *ph1 = nullptr, *plog = nullptr;
    cudaGetSymbolAddress((void**)&px,    g_x);
    cudaGetSymbolAddress((void**)&pwihp, g_wWihp);
    cudaGetSymbolAddress((void**)&pwx,   g_wxproj);
    cudaGetSymbolAddress((void**)&penc,  g_enc);
    cudaGetSymbolAddress((void**)&ph1,   g_h1);
    cudaGetSymbolAddress((void**)&plog,  g_logits);
    float* pwihp0 = pwihp;
    float* pwihp1 = pwihp + (size_t)4 * Hw_ * Kp_;
    float* pwx0 = pwx;
    float* pwx1 = pwx + (size_t)NC_ * 4 * Hw_;

    // 0) clear output + initial states
    zero_out_kernel<<<512, 256>>>(out, out_size);
    zero_state_kernel<<<(2 * 2 * NC_ * Hc_ + 255) / 256, 256>>>();
    pad_wih_kernel<<<(2 * 4 * Hw_ * Kp_ + 255) / 256, 256>>>(wWih_f, wWih_b);

    // 1) char BiLSTM, fused gates+cell per step
    for (int t = 0; t < W_; t++) {
        char_step_kernel<<<dim3(Hc_ / 32, NC_ / 64, 2), 256>>>(
            char_inputs, t, char_emb,
            cWih_f, cWhh_f, cbih_f, cbhh_f,
            cWih_b, cWhh_b, cbih_b, cbhh_b);
    }

    // 2) build padded word input
    build_x_kernel<<<(NC_ * Kp_ + 255) / 256, 256>>>(word_inputs, cap_inputs, word_emb, cap_emb);

    // 3) word input projections (biases folded)
    mma_gemm<<<dim3(4 * Hw_ / 128, NC_ / 128), 256>>>(
        px, pwihp0, wbih_f, wbhh_f, pwx0, NC_, 4 * Hw_, Kp_, 0);
    mma_gemm<<<dim3(4 * Hw_ / 128, NC_ / 128), 256>>>(
        px, pwihp1, wbih_b, wbhh_b, pwx1, NC_, 4 * Hw_, Kp_, 0);

    // 4) word BiLSTM, fused gates+cell per step
    for (int t = 0; t < S_; t++) {
        word_step_kernel<<<dim3(Hw_ / 16, 1, 2), 256>>>(wWhh_f, wWhh_b, t);
    }

    // 5) feed-forward head
    mma_gemm<<<dim3(Hw_ / 128, NC_ / 128), 256>>>(
        penc, ff1_W, ff1_b, nullptr, ph1, NC_, Hw_, 2 * Hw_, 1 /*tanh*/);
    mma_gemm<<<dim3(1, NC_ / 128), 256>>>(
        ph1, ff2_W, ff2_b, nullptr, plog, NC_, T_, Hw_, 0);

    // 6) CRF loss + Viterbi decode
    crf_alpha_kernel<<<B_, T_>>>(trans, start_trans, end_trans);
    crf_loss_kernel<<<1, B_>>>(tag_inputs, trans, start_trans, end_trans, out, out_size);
    viterbi_kernel<<<B_, T_>>>(trans, start_trans, end_trans, out, out_size);
}

// round 4
// speedup vs baseline: 2.1726x; 1.4173x over previous
#include <cuda_runtime.h>
#include <math.h>

// ---------------- problem constants ----------------
#define S_   256
#define B_   64
#define W_   16
#define Ec_  64
#define Hc_  128
#define E_   300
#define Hw_  512
#define T_   32
#define D_   557           // 1 + E + 2*Hc
#define Kp_  576           // D padded to multiple of 16
#define NC_  (B_ * S_)     // 16384 words for char encoder
#define VC_  128           // char vocab

// ---------------- scratch (device globals; no allocs allowed) ----------------
__device__ float g_ch_hi[2][2][NC_ * Hc_];     // char h, tf32-hi, [dir][buf]
__device__ float g_ch_lo[2][2][NC_ * Hc_];     // char h, tf32-lo
__device__ float g_char_c[2][NC_ * Hc_];
__device__ float g_cproj[2][VC_ * 4 * Hc_];    // per-vocab emb@Wih^T + biases
__device__ float g_cwhh_hi[2][4 * Hc_ * Hc_];
__device__ float g_cwhh_lo[2][4 * Hc_ * Hc_];
__device__ float g_x_hi[NC_ * Kp_];
__device__ float g_x_lo[NC_ * Kp_];
__device__ float g_wih_hi[2][4 * Hw_ * Kp_];   // padded word Wih split
__device__ float g_wih_lo[2][4 * Hw_ * Kp_];
__device__ float g_wxproj[2][(size_t)NC_ * 4 * Hw_];
__device__ float g_wh_hi[2][2][B_ * Hw_];
__device__ float g_wh_lo[2][2][B_ * Hw_];
__device__ float g_word_c[2][B_ * Hw_];
__device__ float g_enc_hi[(size_t)NC_ * 2 * Hw_];
__device__ float g_enc_lo[(size_t)NC_ * 2 * Hw_];
__device__ float g_h1_hi[(size_t)NC_ * Hw_];
__device__ float g_h1_lo[(size_t)NC_ * Hw_];
__device__ float g_ff1w_hi[Hw_ * 2 * Hw_];
__device__ float g_ff1w_lo[Hw_ * 2 * Hw_];
__device__ float g_ff2w_hi[T_ * Hw_];
__device__ float g_ff2w_lo[T_ * Hw_];
__device__ float g_logits[NC_ * T_];
__device__ float g_logZ[B_];
__device__ volatile int g_bar_count[2];
__device__ volatile int g_bar_gen[2];

__device__ __forceinline__ float sigf(float x) { return 1.0f / (1.0f + expf(-x)); }

__device__ __forceinline__ unsigned f2tf(float f) {
    unsigned u;
    asm("cvt.rna.tf32.f32 %0, %1;" : "=r"(u) : "f"(f));
    return u;
}
__device__ __forceinline__ float fu(unsigned u) { return __uint_as_float(u); }
__device__ __forceinline__ unsigned uf(float f) { return __float_as_uint(f); }
// split fp32 into tf32 hi/lo stored as floats
__device__ __forceinline__ void split2(float v, float& hi, float& lo) {
    unsigned h = f2tf(v);
    hi = fu(h);
    lo = fu(f2tf(v - fu(h)));
}

__device__ __forceinline__ void mma8(float* c, const unsigned* a, const unsigned* b) {
    asm volatile(
        "mma.sync.aligned.m16n8k8.row.col.f32.tf32.tf32.f32 "
        "{%0,%1,%2,%3}, {%4,%5,%6,%7}, {%8,%9}, {%0,%1,%2,%3};"
        : "+f"(c[0]), "+f"(c[1]), "+f"(c[2]), "+f"(c[3])
        : "r"(a[0]), "r"(a[1]), "r"(a[2]), "r"(a[3]), "r"(b[0]), "r"(b[1]));
}
__device__ __forceinline__ void mma3(float* c, const unsigned* ah, const unsigned* al,
                                     const unsigned* bh, const unsigned* bl) {
    mma8(c, al, bh);
    mma8(c, ah, bl);
    mma8(c, ah, bh);
}

// ---------------- utility / prep kernels ----------------
__global__ void zero_out_kernel(float* o, int n) {
    for (int i = blockIdx.x * blockDim.x + threadIdx.x; i < n; i += gridDim.x * blockDim.x)
        o[i] = 0.0f;
}

__global__ void zero_state_kernel() {
    int stride = gridDim.x * blockDim.x;
    int i0 = blockIdx.x * blockDim.x + threadIdx.x;
    for (int i = i0; i < 2 * 2 * NC_ * Hc_; i += stride) {
        (&g_ch_hi[0][0][0])[i] = 0.0f;
        (&g_ch_lo[0][0][0])[i] = 0.0f;
    }
    for (int i = i0; i < 2 * NC_ * Hc_; i += stride)
        (&g_char_c[0][0])[i] = 0.0f;
    for (int i = i0; i < 2 * 2 * B_ * Hw_; i += stride) {
        (&g_wh_hi[0][0][0])[i] = 0.0f;
        (&g_wh_lo[0][0][0])[i] = 0.0f;
    }
    for (int i = i0; i < 2 * B_ * Hw_; i += stride)
        (&g_word_c[0][0])[i] = 0.0f;
}

// generic elementwise split
__global__ void split_arr_kernel(const float* __restrict__ src,
                                 float* __restrict__ hi, float* __restrict__ lo, int n) {
    int i = blockIdx.x * blockDim.x + threadIdx.x;
    if (i < n) split2(src[i], hi[i], lo[i]);
}

// pad + split word Wih (both dirs)
__global__ void pad_split_wih(const float* __restrict__ Wf, const float* __restrict__ Wb) {
    int idx = blockIdx.x * blockDim.x + threadIdx.x;
    const int per = 4 * Hw_ * Kp_;
    if (idx >= 2 * per) return;
    int dir = idx / per;
    int r = idx - dir * per;
    int n = r / Kp_, k = r - n * Kp_;
    const float* Wsrc = dir ? Wb : Wf;
    float v = (k < D_) ? Wsrc[(size_t)n * D_ + k] : 0.0f;
    split2(v, g_wih_hi[dir][r], g_wih_lo[dir][r]);
}

// per-vocab char emb projection: proj[dir][cid][n] = emb[cid]@Wih[n]^T + bih[n] + bhh[n]
__global__ void __launch_bounds__(256)
char_vocab_proj(const float* __restrict__ emb,
                const float* __restrict__ WihF, const float* __restrict__ bihF,
                const float* __restrict__ bhhF,
                const float* __restrict__ WihB, const float* __restrict__ bihB,
                const float* __restrict__ bhhB)
{
    int dir = blockIdx.x >> 7;
    int cid = blockIdx.x & 127;
    const float* Wih = dir ? WihB : WihF;
    const float* bih = dir ? bihB : bihF;
    const float* bhh = dir ? bhhB : bhhF;
    __shared__ float e[Ec_];
    if (threadIdx.x < Ec_) e[threadIdx.x] = emb[cid * Ec_ + threadIdx.x];
    __syncthreads();
    for (int n = threadIdx.x; n < 4 * Hc_; n += 256) {
        float s = bih[n] + bhh[n];
        const float* wr = &Wih[(size_t)n * Ec_];
#pragma unroll 8
        for (int k = 0; k < Ec_; k++) s += e[k] * wr[k];
        g_cproj[dir][cid * 4 * Hc_ + n] = s;
    }
}

// build padded word input x = [we | cf | ce | 0pad], split at write
__global__ void __launch_bounds__(256)
build_x_kernel(const int* __restrict__ wid, const int* __restrict__ cap,
               const float* __restrict__ wemb, const float* __restrict__ cemb)
{
    int idx = blockIdx.x * blockDim.x + threadIdx.x;
    if (idx >= NC_ * Kp_) return;
    int d = idx % Kp_;
    int sb = idx / Kp_;
    int s = sb / B_, b = sb % B_;
    float v = 0.0f;
    if (d < E_) {
        v = wemb[(size_t)wid[s * B_ + b] * E_ + d];
    } else if (d < E_ + 2 * Hc_) {
        int j = d - E_;
        int n = b * S_ + s;
        v = (j < Hc_) ? (g_ch_hi[0][0][(size_t)n * Hc_ + j] + g_ch_lo[0][0][(size_t)n * Hc_ + j])
                      : (g_ch_hi[1][0][(size_t)n * Hc_ + (j - Hc_)] + g_ch_lo[1][0][(size_t)n * Hc_ + (j - Hc_)]);
    } else if (d == E_ + 2 * Hc_) {
        v = cemb[cap[s * B_ + b]];
    }
    split2(v, g_x_hi[idx], g_x_lo[idx]);
}

// ---------------- pre-split 3xTF32 GEMM: C = act(A @ W^T + b1 + b2) ------------
// A hi/lo: (M,K), W hi/lo: (N,K). M%128==0, K%16==0. Tile 128x128x16.
__global__ void __launch_bounds__(256)
mma_gemm_split(const float* __restrict__ AH, const float* __restrict__ AL,
               const float* __restrict__ WH, const float* __restrict__ WL,
               const float* __restrict__ b1, const float* __restrict__ b2,
               float* __restrict__ C, float* __restrict__ Clo,
               int M, int N, int K, int act)
{
    __shared__ __align__(16) float sm[4 * 128 * 20];
    float* AsH = sm;
    float* AsL = sm + 2560;
    float* WsH = sm + 5120;
    float* WsL = sm + 7680;
    const int tid = threadIdx.x;
    const int w = tid >> 5, l = tid & 31;
    const int wm = w & 1, wn = w >> 1;
    const int g = l >> 2, tg = l & 3;
    const int m0 = blockIdx.y * 128, n0 = blockIdx.x * 128;

    float acc[4][4][4] = {};
    const int r = tid >> 2, c4 = (tid & 3) * 4;

    for (int k0 = 0; k0 < K; k0 += 16) {
#pragma unroll
        for (int h = 0; h < 2; h++) {
            int rr = r + h * 64;
            size_t aoff = (size_t)(m0 + rr) * K + k0 + c4;
            *(float4*)&AsH[rr * 20 + c4] = *(const float4*)&AH[aoff];
            *(float4*)&AsL[rr * 20 + c4] = *(const float4*)&AL[aoff];
            int n = n0 + rr;
            float4 vh = make_float4(0.f, 0.f, 0.f, 0.f), vl = vh;
            if (n < N) {
                size_t woff = (size_t)n * K + k0 + c4;
                vh = *(const float4*)&WH[woff];
                vl = *(const float4*)&WL[woff];
            }
            *(float4*)&WsH[rr * 20 + c4] = vh;
            *(float4*)&WsL[rr * 20 + c4] = vl;
        }
        __syncthreads();
#pragma unroll
        for (int ks = 0; ks < 2; ks++) {
            unsigned ah[4][4], al[4][4], bh[4][2], bl[4][2];
#pragma unroll
            for (int mi = 0; mi < 4; mi++) {
                int rb = (wm * 64 + mi * 16 + g) * 20 + ks * 8 + tg;
                ah[mi][0] = uf(AsH[rb]);       al[mi][0] = uf(AsL[rb]);
                ah[mi][1] = uf(AsH[rb + 160]); al[mi][1] = uf(AsL[rb + 160]);
                ah[mi][2] = uf(AsH[rb + 4]);   al[mi][2] = uf(AsL[rb + 4]);
                ah[mi][3] = uf(AsH[rb + 164]); al[mi][3] = uf(AsL[rb + 164]);
            }
#pragma unroll
            for (int ni = 0; ni < 4; ni++) {
                int nb = (wn * 32 + ni * 8 + g) * 20 + ks * 8 + tg;
                bh[ni][0] = uf(WsH[nb]);     bl[ni][0] = uf(WsL[nb]);
                bh[ni][1] = uf(WsH[nb + 4]); bl[ni][1] = uf(WsL[nb + 4]);
            }
#pragma unroll
            for (int mi = 0; mi < 4; mi++)
#pragma unroll
                for (int ni = 0; ni < 4; ni++)
                    mma3(acc[mi][ni], ah[mi], al[mi], bh[ni], bl[ni]);
        }
        __syncthreads();
    }
#pragma unroll
    for (int mi = 0; mi < 4; mi++) {
#pragma unroll
        for (int ni = 0; ni < 4; ni++) {
            int m = m0 + wm * 64 + mi * 16 + g;
            int n = n0 + wn * 32 + ni * 8 + 2 * tg;
#pragma unroll
            for (int q = 0; q < 4; q++) {
                int mm = m + (q >> 1) * 8;
                int nn = n + (q & 1);
                if (nn >= N) continue;
                float v = acc[mi][ni][q];
                if (b1) v += b1[nn];
                if (b2) v += b2[nn];
                if (act == 1) v = tanhf(v);
                size_t off = (size_t)mm * N + nn;
                if (Clo) split2(v, C[off], Clo[off]);
                else C[off] = v;
            }
        }
    }
}

// ---------------- fused char LSTM step, K=128 (h@Whh only) ----------------------
// grid (4, 256, 2), block 256. tile M=64 words, N=128 (4 gates x 32 j), K=128
__global__ void __launch_bounds__(256)
char_step_kernel(const int* __restrict__ cin, int t)
{
    const int dir = blockIdx.z;
    const int t_eff = dir ? (W_ - 1 - t) : t;
    const float* hpH = g_ch_hi[dir][t & 1];
    const float* hpL = g_ch_lo[dir][t & 1];
    float* hnH = g_ch_hi[dir][(t + 1) & 1];
    float* hnL = g_ch_lo[dir][(t + 1) & 1];
    float* cst = g_char_c[dir];
    const float* WhiS = g_cwhh_hi[dir];
    const float* WloS = g_cwhh_lo[dir];
    const float* proj = g_cproj[dir];

    __shared__ __align__(16) float sm[64 * 132];
    float* AsH = sm;
    float* AsL = sm + 1280;
    float* WsH = sm + 2560;
    float* WsL = sm + 5120;  // ends 7680 < 8448
    float (*zb)[132] = (float(*)[132])sm;

    const int tid = threadIdx.x;
    const int w = tid >> 5, l = tid & 31;
    const int wm = w & 1, wn = w >> 1;
    const int g = l >> 2, tg = l & 3;
    const int j0 = blockIdx.x * 32;
    const int m0 = blockIdx.y * 64;

    float acc[2][4][4] = {};
    const int r = tid >> 2, c4 = (tid & 3) * 4;

#pragma unroll
    for (int kk = 0; kk < 8; kk++) {
        int k0 = kk * 16;
        {
            size_t aoff = (size_t)(m0 + r) * Hc_ + k0 + c4;
            *(float4*)&AsH[r * 20 + c4] = *(const float4*)&hpH[aoff];
            *(float4*)&AsL[r * 20 + c4] = *(const float4*)&hpL[aoff];
        }
#pragma unroll
        for (int h = 0; h < 2; h++) {
            int rr = r + h * 64;
            int wr = (rr >> 5) * Hc_ + j0 + (rr & 31);
            size_t woff = (size_t)wr * Hc_ + k0 + c4;
            *(float4*)&WsH[rr * 20 + c4] = *(const float4*)&WhiS[woff];
            *(float4*)&WsL[rr * 20 + c4] = *(const float4*)&WloS[woff];
        }
        __syncthreads();
#pragma unroll
        for (int ks = 0; ks < 2; ks++) {
            unsigned ah[2][4], al[2][4], bh[4][2], bl[4][2];
#pragma unroll
            for (int mi = 0; mi < 2; mi++) {
                int rb = (wm * 32 + mi * 16 + g) * 20 + ks * 8 + tg;
                ah[mi][0] = uf(AsH[rb]);       al[mi][0] = uf(AsL[rb]);
                ah[mi][1] = uf(AsH[rb + 160]); al[mi][1] = uf(AsL[rb + 160]);
                ah[mi][2] = uf(AsH[rb + 4]);   al[mi][2] = uf(AsL[rb + 4]);
                ah[mi][3] = uf(AsH[rb + 164]); al[mi][3] = uf(AsL[rb + 164]);
            }
#pragma unroll
            for (int ni = 0; ni < 4; ni++) {
                int nb = (wn * 32 + ni * 8 + g) * 20 + ks * 8 + tg;
                bh[ni][0] = uf(WsH[nb]);     bl[ni][0] = uf(WsL[nb]);
                bh[ni][1] = uf(WsH[nb + 4]); bl[ni][1] = uf(WsL[nb + 4]);
            }
#pragma unroll
            for (int mi = 0; mi < 2; mi++)
#pragma unroll
                for (int ni = 0; ni < 4; ni++)
                    mma3(acc[mi][ni], ah[mi], al[mi], bh[ni], bl[ni]);
        }
        __syncthreads();
    }
    // stage z (overlays tiles)
#pragma unroll
    for (int mi = 0; mi < 2; mi++) {
#pragma unroll
        for (int ni = 0; ni < 4; ni++) {
            int row = wm * 32 + mi * 16 + g;
            int col = wn * 32 + ni * 8 + 2 * tg;
            zb[row][col]         = acc[mi][ni][0];
            zb[row][col + 1]     = acc[mi][ni][1];
            zb[row + 8][col]     = acc[mi][ni][2];
            zb[row + 8][col + 1] = acc[mi][ni][3];
        }
    }
    __syncthreads();
    // cell update (adds vocab projection)
    for (int idx = tid; idx < 64 * 32; idx += 256) {
        int ml = idx >> 5, jj = idx & 31;
        int j = j0 + jj;
        int m = m0 + ml;
        int cid = cin[m * W_ + t_eff];
        const float* pr = &proj[(size_t)cid * 4 * Hc_];
        float zi = zb[ml][jj]      + pr[j];
        float zf = zb[ml][32 + jj] + pr[Hc_ + j];
        float zg = zb[ml][64 + jj] + pr[2 * Hc_ + j];
        float zo = zb[ml][96 + jj] + pr[3 * Hc_ + j];
        size_t off = (size_t)m * Hc_ + j;
        float c = cst[off];
        c = sigf(zf) * c + sigf(zi) * tanhf(zg);
        cst[off] = c;
        float hv = sigf(zo) * tanhf(c);
        split2(hv, hnH[off], hnL[off]);
    }
}

// ---------------- persistent word BiLSTM ----------------------------------------
// 128 blocks (64 per dir), 256 threads. Each block owns j-tile of 8 (32 weight
// rows x K=512), cached pre-split in smem for all 256 steps. Grid barrier per dir.
#define WP_SMEM_FLOATS (2 * 32 * 516 + 2 * 64 * 68)
__device__ __forceinline__ void grid_bar_dir(int dir) {
    __syncthreads();
    if (threadIdx.x == 0) {
        __threadfence();
        int gen = g_bar_gen[dir];
        if (atomicAdd((int*)&g_bar_count[dir], 1) == 63) {
            g_bar_count[dir] = 0;
            __threadfence();
            g_bar_gen[dir] = gen + 1;
        } else {
            while (g_bar_gen[dir] == gen) __nanosleep(20);
            __threadfence();
        }
    }
    __syncthreads();
}

__global__ void __launch_bounds__(256)
word_persistent(const float* __restrict__ WhhF, const float* __restrict__ WhhB)
{
    extern __shared__ float sm[];
    float* WH = sm;                       // 32 x 516
    float* WL = sm + 32 * 516;
    float* AH = sm + 2 * 32 * 516;        // 64 x 68
    float* AL = AH + 64 * 68;
    float (*zb)[36] = (float(*)[36])AH;   // overlay (2304 < 4352)

    const int dir = blockIdx.x >> 6;
    const int jb = blockIdx.x & 63;
    const int j0 = jb * 8;
    const int tid = threadIdx.x;
    const int w = tid >> 5, l = tid & 31;
    const int wm = w & 3, wn = w >> 2;
    const int g = l >> 2, tg = l & 3;

    const float* Whh = dir ? WhhB : WhhF;
    // load + split this block's weight slice once
    for (int i = tid; i < 32 * 512; i += 256) {
        int rr = i >> 9, k = i & 511;
        int wr = (rr >> 3) * Hw_ + j0 + (rr & 7);
        split2(Whh[(size_t)wr * Hw_ + k], WH[rr * 516 + k], WL[rr * 516 + k]);
    }
    __syncthreads();

    const float* xbase = g_wxproj[dir];
    float* cst = g_word_c[dir];

    for (int t = 0; t < S_; t++) {
        const int s = dir ? (S_ - 1 - t) : t;
        const float* hpH = g_wh_hi[dir][t & 1];
        const float* hpL = g_wh_lo[dir][t & 1];
        float* hnH = g_wh_hi[dir][(t + 1) & 1];
        float* hnL = g_wh_lo[dir][(t + 1) & 1];

        float acc[2][4] = {};
#pragma unroll 1
        for (int ko = 0; ko < 8; ko++) {
#pragma unroll
            for (int q = 0; q < 4; q++) {
                int idx = tid + q * 256;
                int row = idx >> 4, col = (idx & 15) * 4;
                size_t goff = (size_t)row * Hw_ + ko * 64 + col;
                *(float4*)&AH[row * 68 + col] = *(const float4*)&hpH[goff];
                *(float4*)&AL[row * 68 + col] = *(const float4*)&hpL[goff];
            }
            __syncthreads();
#pragma unroll
            for (int k8 = 0; k8 < 8; k8++) {
                int kc = k8 * 8;
                unsigned ah[4], al[4];
                int rb = (wm * 16 + g) * 68 + kc + tg;
                ah[0] = uf(AH[rb]);           al[0] = uf(AL[rb]);
                ah[1] = uf(AH[rb + 8 * 68]);  al[1] = uf(AL[rb + 8 * 68]);
                ah[2] = uf(AH[rb + 4]);       al[2] = uf(AL[rb + 4]);
                ah[3] = uf(AH[rb + 8 * 68 + 4]); al[3] = uf(AL[rb + 8 * 68 + 4]);
#pragma unroll
                for (int ni = 0; ni < 2; ni++) {
                    int nb = (wn * 16 + ni * 8 + g) * 516 + ko * 64 + kc + tg;
                    unsigned bh[2], bl[2];
                    bh[0] = uf(WH[nb]);     bl[0] = uf(WL[nb]);
                    bh[1] = uf(WH[nb + 4]); bl[1] = uf(WL[nb + 4]);
                    mma3(acc[ni], ah, al, bh, bl);
                }
            }
            __syncthreads();
        }
        // stage z (overlay AH region; safe after last sync)
#pragma unroll
        for (int ni = 0; ni < 2; ni++) {
            int row = wm * 16 + g;
            int col = wn * 16 + ni * 8 + 2 * tg;
            zb[row][col]         = acc[ni][0];
            zb[row][col + 1]     = acc[ni][1];
            zb[row + 8][col]     = acc[ni][2];
            zb[row + 8][col + 1] = acc[ni][3];
        }
        __syncthreads();
        // cell update: 64 b x 8 j
        for (int idx = tid; idx < 512; idx += 256) {
            int b = idx >> 3, jj = idx & 7;
            int j = j0 + jj;
            const float* xr = xbase + ((size_t)s * B_ + b) * 4 * Hw_;
            float zi = zb[b][jj]      + xr[j];
            float zf = zb[b][8 + jj]  + xr[Hw_ + j];
            float zg = zb[b][16 + jj] + xr[2 * Hw_ + j];
            float zo = zb[b][24 + jj] + xr[3 * Hw_ + j];
            size_t off = (size_t)b * Hw_ + j;
            float c = cst[off];
            c = sigf(zf) * c + sigf(zi) * tanhf(zg);
            cst[off] = c;
            float hv = sigf(zo) * tanhf(c);
            float hh, hl;
            split2(hv, hh, hl);
            hnH[off] = hh; hnL[off] = hl;
            size_t eoff = ((size_t)s * B_ + b) * (2 * Hw_) + dir * Hw_ + j;
            g_enc_hi[eoff] = hh; g_enc_lo[eoff] = hl;
        }
        grid_bar_dir(dir);
    }
}

// ---------------- CRF forward (logZ per batch) ----------------
__global__ void __launch_bounds__(32)
crf_alpha_kernel(const float* __restrict__ trans, const float* __restrict__ start,
                 const float* __restrict__ endv)
{
    __shared__ float tr[T_][T_];
    __shared__ float alpha[T_];
    const int b = blockIdx.x;
    const int to = threadIdx.x;
    for (int i = to; i < T_ * T_; i += T_) tr[i / T_][i % T_] = trans[i];
    alpha[to] = start[to] + g_logits[(size_t)(0 * B_ + b) * T_ + to];
    __syncthreads();
    for (int s = 1; s < S_; s++) {
        float m = -1e30f;
#pragma unroll
        for (int f = 0; f < T_; f++) m = fmaxf(m, alpha[f] + tr[f][to]);
        float sum = 0.0f;
#pragma unroll
        for (int f = 0; f < T_; f++) sum += expf(alpha[f] + tr[f][to] - m);
        float a = m + logf(sum) + g_logits[((size_t)s * B_ + b) * T_ + to];
        __syncthreads();
        alpha[to] = a;
        __syncthreads();
    }
    float v = alpha[to] + endv[to];
    float m = v;
#pragma unroll
    for (int o = 16; o > 0; o >>= 1) m = fmaxf(m, __shfl_xor_sync(0xffffffffu, m, o));
    float e = expf(v - m);
#pragma unroll
    for (int o = 16; o > 0; o >>= 1) e += __shfl_xor_sync(0xffffffffu, e, o);
    if (to == 0) g_logZ[b] = m + logf(e);
}

// ---------------- CRF gold score + loss ----------------
__global__ void __launch_bounds__(64)
crf_loss_kernel(const int* __restrict__ tags, const float* __restrict__ trans,
                const float* __restrict__ start, const float* __restrict__ endv,
                float* __restrict__ out, int out_size)
{
    __shared__ float red[B_];
    const int b = threadIdx.x;
    int prev = tags[0 * B_ + b];
    float score = start[prev];
    for (int s = 0; s < S_; s++) {
        int tg = tags[s * B_ + b];
        score += g_logits[((size_t)s * B_ + b) * T_ + tg];
        if (s > 0) score += trans[prev * T_ + tg];
        prev = tg;
    }
    score += endv[prev];
    red[b] = g_logZ[b] - score;
    __syncthreads();
    if (b == 0) {
        float t = 0.0f;
        for (int i = 0; i < B_; i++) t += red[i];
        if (out_size > 0) out[0] = t;
    }
}

// ---------------- Viterbi decode ----------------
__global__ void __launch_bounds__(32)
viterbi_kernel(const float* __restrict__ trans, const float* __restrict__ start,
               const float* __restrict__ endv, float* __restrict__ out, int out_size)
{
    __shared__ float tr[T_][T_];
    __shared__ float v[T_];
    __shared__ unsigned char bp[S_ - 1][T_];
    const int b = blockIdx.x;
    const int to = threadIdx.x;
    for (int i = to; i < T_ * T_; i += T_) tr[i / T_][i % T_] = trans[i];
    v[to] = start[to] + g_logits[(size_t)b * T_ + to];
    __syncthreads();
    for (int s = 1; s < S_; s++) {
        float best = -1e30f;
        int arg = 0;
#pragma unroll
        for (int f = 0; f < T_; f++) {
            float sc = v[f] + tr[f][to];
            if (sc > best) { best = sc; arg = f; }
        }
        bp[s - 1][to] = (unsigned char)arg;
        float nv = best + g_logits[((size_t)s * B_ + b) * T_ + to];
        __syncthreads();
        v[to] = nv;
        __syncthreads();
    }
    if (to == 0) {
        float best = -1e30f;
        int last = 0;
        for (int f = 0; f < T_; f++) {
            float sc = v[f] + endv[f];
            if (sc > best) { best = sc; last = f; }
        }
        int tag = last;
        int base = 1 + b * S_;
        if (base + S_ - 1 < out_size) out[base + S_ - 1] = (float)tag;
        for (int s = S_ - 2; s >= 0; s--) {
            tag = bp[s][tag];
            if (base + s < out_size) out[base + s] = (float)tag;
        }
    }
}

// ---------------- host-side orchestration ----------------
extern "C" void kernel_launch(void* const* d_in, const int* in_sizes, int n_in,
                              void* d_out, int out_size) {
    (void)in_sizes; (void)n_in;
    const int*   word_inputs = (const int*)d_in[0];
    const int*   char_inputs = (const int*)d_in[1];
    const int*   cap_inputs  = (const int*)d_in[2];
    const int*   tag_inputs  = (const int*)d_in[3];
    const float* word_emb    = (const float*)d_in[4];
    const float* cap_emb     = (const float*)d_in[5];
    const float* char_emb    = (const float*)d_in[6];
    const float* cWih_f = (const float*)d_in[7];
    const float* cWhh_f = (const float*)d_in[8];
    const float* cbih_f = (const float*)d_in[9];
    const float* cbhh_f = (const float*)d_in[10];
    const float* cWih_b = (const float*)d_in[11];
    const float* cWhh_b = (const float*)d_in[12];
    const float* cbih_b = (const float*)d_in[13];
    const float* cbhh_b = (const float*)d_in[14];
    const float* wWih_f = (const float*)d_in[15];
    const float* wWhh_f = (const float*)d_in[16];
    const float* wbih_f = (const float*)d_in[17];
    const float* wbhh_f = (const float*)d_in[18];
    const float* wWih_b = (const float*)d_in[19];
    const float* wWhh_b = (const float*)d_in[20];
    const float* wbih_b = (const float*)d_in[21];
    const float* wbhh_b = (const float*)d_in[22];
    const float* ff1_W  = (const float*)d_in[23];
    const float* ff1_b  = (const float*)d_in[24];
    const float* ff2_W  = (const float*)d_in[25];
    const float* ff2_b  = (const float*)d_in[26];
    const float* trans  = (const float*)d_in[27];
    const float* start_trans = (const float*)d_in[28];
    const float* end_trans   = (const float*)d_in[29];
    float* out = (float*)d_out;

    float *pxh, *pxl, *pwih_h, *pwih_l, *pwx, *pench, *pencl, *ph1h, *ph1l, *plog;
    float *pcwhh_h, *pcwhh_l, *pff1h, *pff1l, *pff2h, *pff2l;
    cudaGetSymbolAddress((void**)&pxh,     g_x_hi);
    cudaGetSymbolAddress((void**)&pxl,     g_x_lo);
    cudaGetSymbolAddress((void**)&pwih_h,  g_wih_hi);
    cudaGetSymbolAddress((void**)&pwih_l,  g_wih_lo);
    cudaGetSymbolAddress((void**)&pwx,     g_wxproj);
    cudaGetSymbolAddress((void**)&pench,   g_enc_hi);
    cudaGetSymbolAddress((void**)&pencl,   g_enc_lo);
    cudaGetSymbolAddress((void**)&ph1h,    g_h1_hi);
    cudaGetSymbolAddress((void**)&ph1l,    g_h1_lo);
    cudaGetSymbolAddress((void**)&plog,    g_logits);
    cudaGetSymbolAddress((void**)&pcwhh_h, g_cwhh_hi);
    cudaGetSymbolAddress((void**)&pcwhh_l, g_cwhh_lo);
    cudaGetSymbolAddress((void**)&pff1h,   g_ff1w_hi);
    cudaGetSymbolAddress((void**)&pff1l,   g_ff1w_lo);
    cudaGetSymbolAddress((void**)&pff2h,   g_ff2w_hi);
    cudaGetSymbolAddress((void**)&pff2l,   g_ff2w_lo);

    const size_t wih_per = (size_t)4 * Hw_ * Kp_;
    const size_t wx_per = (size_t)NC_ * 4 * Hw_;
    const int cwhh_n = 4 * Hc_ * Hc_;

    // 0) init + weight prep
    zero_out_kernel<<<512, 256>>>(out, out_size);
    zero_state_kernel<<<2048, 256>>>();
    pad_split_wih<<<(int)((2 * wih_per + 255) / 256), 256>>>(wWih_f, wWih_b);
    split_arr_kernel<<<(cwhh_n + 255) / 256, 256>>>(cWhh_f, pcwhh_h, pcwhh_l, cwhh_n);
    split_arr_kernel<<<(cwhh_n + 255) / 256, 256>>>(cWhh_b, pcwhh_h + cwhh_n, pcwhh_l + cwhh_n, cwhh_n);
    split_arr_kernel<<<(Hw_ * 2 * Hw_ + 255) / 256, 256>>>(ff1_W, pff1h, pff1l, Hw_ * 2 * Hw_);
    split_arr_kernel<<<(T_ * Hw_ + 255) / 256, 256>>>(ff2_W, pff2h, pff2l, T_ * Hw_);
    char_vocab_proj<<<2 * VC_, 256>>>(char_emb, cWih_f, cbih_f, cbhh_f, cWih_b, cbih_b, cbhh_b);

    // 1) char BiLSTM (fused, K=128)
    for (int t = 0; t < W_; t++)
        char_step_kernel<<<dim3(4, NC_ / 64, 2), 256>>>(char_inputs, t);

    // 2) build padded + split word input
    build_x_kernel<<<(NC_ * Kp_ + 255) / 256, 256>>>(word_inputs, cap_inputs, word_emb, cap_emb);

    // 3) word input projections
    mma_gemm_split<<<dim3(4 * Hw_ / 128, NC_ / 128), 256>>>(
        pxh, pxl, pwih_h, pwih_l, wbih_f, wbhh_f, pwx, nullptr, NC_, 4 * Hw_, Kp_, 0);
    mma_gemm_split<<<dim3(4 * Hw_ / 128, NC_ / 128), 256>>>(
        pxh, pxl, pwih_h + wih_per, pwih_l + wih_per, wbih_b, wbhh_b,
        pwx + wx_per, nullptr, NC_, 4 * Hw_, Kp_, 0);

    // 4) persistent word BiLSTM (both dirs, all 256 steps, one launch)
    static int wp_attr_done = 0;
    (void)wp_attr_done;
    cudaFuncSetAttribute(word_persistent, cudaFuncAttributeMaxDynamicSharedMemorySize,
                         WP_SMEM_FLOATS * (int)sizeof(float));
    word_persistent<<<128, 256, WP_SMEM_FLOATS * sizeof(float)>>>(wWhh_f, wWhh_b);

    // 5) feed-forward head
    mma_gemm_split<<<dim3(Hw_ / 128, NC_ / 128), 256>>>(
        pench, pencl, pff1h, pff1l, ff1_b, nullptr, ph1h, ph1l, NC_, Hw_, 2 * Hw_, 1);
    mma_gemm_split<<<dim3(1, NC_ / 128), 256>>>(
        ph1h, ph1l, pff2h, pff2l, ff2_b, nullptr, plog, nullptr, NC_, T_, Hw_, 0);

    // 6) CRF loss + Viterbi
    crf_alpha_kernel<<<B_, T_>>>(trans, start_trans, end_trans);
    crf_loss_kernel<<<1, B_>>>(tag_inputs, trans, start_trans, end_trans, out, out_size);
    viterbi_kernel<<<B_, T_>>>(trans, start_trans, end_trans, out, out_size);
}

// round 6
// speedup vs baseline: 2.5125x; 1.1564x over previous
#include <cuda_runtime.h>
#include <stdint.h>
#include <math.h>

// ---------------- problem constants ----------------
#define S_   256
#define B_   64
#define W_   16
#define Ec_  64
#define Hc_  128
#define E_   300
#define Hw_  512
#define T_   32
#define D_   557           // 1 + E + 2*Hc
#define Kp_  576           // D padded to multiple of 16
#define NC_  (B_ * S_)     // 16384 words for char encoder
#define VC_  128           // char vocab

// ---------------- scratch (device globals; no allocs allowed) ----------------
__device__ float g_ch_hi[2][2][NC_ * Hc_];     // char h, tf32-hi, [dir][buf]
__device__ float g_ch_lo[2][2][NC_ * Hc_];     // char h, tf32-lo
__device__ float g_char_c[2][NC_ * Hc_];
__device__ float g_cproj[2][VC_ * 4 * Hc_];    // per-vocab emb@Wih^T + biases
__device__ float g_cwhh_hi[2][4 * Hc_ * Hc_];
__device__ float g_cwhh_lo[2][4 * Hc_ * Hc_];
__device__ float g_x_hi[NC_ * Kp_];
__device__ float g_x_lo[NC_ * Kp_];
__device__ float g_wih_hi[2][4 * Hw_ * Kp_];   // padded word Wih split
__device__ float g_wih_lo[2][4 * Hw_ * Kp_];
__device__ float g_wxproj[2][(size_t)NC_ * 4 * Hw_];
__device__ float g_wh_hi[2][2][B_ * Hw_];
__device__ float g_wh_lo[2][2][B_ * Hw_];
__device__ float g_word_c[2][B_ * Hw_];
__device__ float g_enc_hi[(size_t)NC_ * 2 * Hw_];
__device__ float g_enc_lo[(size_t)NC_ * 2 * Hw_];
__device__ float g_h1_hi[(size_t)NC_ * Hw_];
__device__ float g_h1_lo[(size_t)NC_ * Hw_];
__device__ float g_ff1w_hi[Hw_ * 2 * Hw_];
__device__ float g_ff1w_lo[Hw_ * 2 * Hw_];
__device__ float g_ff2w_hi[T_ * Hw_];
__device__ float g_ff2w_lo[T_ * Hw_];
__device__ float g_logits[NC_ * T_];
__device__ float g_logZ[B_];
__device__ volatile int g_bar_count[2];
__device__ volatile int g_bar_gen[2];

__device__ __forceinline__ float sigf(float x) { return 1.0f / (1.0f + expf(-x)); }

__device__ __forceinline__ unsigned f2tf(float f) {
    unsigned u;
    asm("cvt.rna.tf32.f32 %0, %1;" : "=r"(u) : "f"(f));
    return u;
}
__device__ __forceinline__ float fu(unsigned u) { return __uint_as_float(u); }
__device__ __forceinline__ unsigned uf(float f) { return __float_as_uint(f); }
__device__ __forceinline__ void split2(float v, float& hi, float& lo) {
    unsigned h = f2tf(v);
    hi = fu(h);
    lo = fu(f2tf(v - fu(h)));
}

__device__ __forceinline__ void mma8(float* c, const unsigned* a, const unsigned* b) {
    asm volatile(
        "mma.sync.aligned.m16n8k8.row.col.f32.tf32.tf32.f32 "
        "{%0,%1,%2,%3}, {%4,%5,%6,%7}, {%8,%9}, {%0,%1,%2,%3};"
        : "+f"(c[0]), "+f"(c[1]), "+f"(c[2]), "+f"(c[3])
        : "r"(a[0]), "r"(a[1]), "r"(a[2]), "r"(a[3]), "r"(b[0]), "r"(b[1]));
}
__device__ __forceinline__ void mma3(float* c, const unsigned* ah, const unsigned* al,
                                     const unsigned* bh, const unsigned* bl) {
    mma8(c, al, bh);
    mma8(c, ah, bl);
    mma8(c, ah, bh);
}

// cp.async helpers
__device__ __forceinline__ void cpa16(uint32_t saddr, const void* gptr) {
    asm volatile("cp.async.ca.shared.global [%0], [%1], 16;" :: "r"(saddr), "l"(gptr));
}
__device__ __forceinline__ void cpa_commit() {
    asm volatile("cp.async.commit_group;");
}
__device__ __forceinline__ void cpa_wait1() {
    asm volatile("cp.async.wait_group 1;");
}
__device__ __forceinline__ void cpa_wait0() {
    asm volatile("cp.async.wait_group 0;");
}

// ---------------- utility / prep kernels ----------------
__global__ void zero_out_kernel(float* o, int n) {
    for (int i = blockIdx.x * blockDim.x + threadIdx.x; i < n; i += gridDim.x * blockDim.x)
        o[i] = 0.0f;
}

__global__ void zero_state_kernel() {
    int stride = gridDim.x * blockDim.x;
    int i0 = blockIdx.x * blockDim.x + threadIdx.x;
    for (int i = i0; i < 2 * 2 * NC_ * Hc_; i += stride) {
        (&g_ch_hi[0][0][0])[i] = 0.0f;
        (&g_ch_lo[0][0][0])[i] = 0.0f;
    }
    for (int i = i0; i < 2 * NC_ * Hc_; i += stride)
        (&g_char_c[0][0])[i] = 0.0f;
    for (int i = i0; i < 2 * 2 * B_ * Hw_; i += stride) {
        (&g_wh_hi[0][0][0])[i] = 0.0f;
        (&g_wh_lo[0][0][0])[i] = 0.0f;
    }
    for (int i = i0; i < 2 * B_ * Hw_; i += stride)
        (&g_word_c[0][0])[i] = 0.0f;
}

__global__ void split_arr_kernel(const float* __restrict__ src,
                                 float* __restrict__ hi, float* __restrict__ lo, int n) {
    int i = blockIdx.x * blockDim.x + threadIdx.x;
    if (i < n) split2(src[i], hi[i], lo[i]);
}

__global__ void pad_split_wih(const float* __restrict__ Wf, const float* __restrict__ Wb) {
    int idx = blockIdx.x * blockDim.x + threadIdx.x;
    const int per = 4 * Hw_ * Kp_;
    if (idx >= 2 * per) return;
    int dir = idx / per;
    int r = idx - dir * per;
    int n = r / Kp_, k = r - n * Kp_;
    const float* Wsrc = dir ? Wb : Wf;
    float v = (k < D_) ? Wsrc[(size_t)n * D_ + k] : 0.0f;
    split2(v, g_wih_hi[dir][r], g_wih_lo[dir][r]);
}

__global__ void __launch_bounds__(256)
char_vocab_proj(const float* __restrict__ emb,
                const float* __restrict__ WihF, const float* __restrict__ bihF,
                const float* __restrict__ bhhF,
                const float* __restrict__ WihB, const float* __restrict__ bihB,
                const float* __restrict__ bhhB)
{
    int dir = blockIdx.x >> 7;
    int cid = blockIdx.x & 127;
    const float* Wih = dir ? WihB : WihF;
    const float* bih = dir ? bihB : bihF;
    const float* bhh = dir ? bhhB : bhhF;
    __shared__ float e[Ec_];
    if (threadIdx.x < Ec_) e[threadIdx.x] = emb[cid * Ec_ + threadIdx.x];
    __syncthreads();
    for (int n = threadIdx.x; n < 4 * Hc_; n += 256) {
        float s = bih[n] + bhh[n];
        const float* wr = &Wih[(size_t)n * Ec_];
#pragma unroll 8
        for (int k = 0; k < Ec_; k++) s += e[k] * wr[k];
        g_cproj[dir][cid * 4 * Hc_ + n] = s;
    }
}

__global__ void __launch_bounds__(256)
build_x_kernel(const int* __restrict__ wid, const int* __restrict__ cap,
               const float* __restrict__ wemb, const float* __restrict__ cemb)
{
    int idx = blockIdx.x * blockDim.x + threadIdx.x;
    if (idx >= NC_ * Kp_) return;
    int d = idx % Kp_;
    int sb = idx / Kp_;
    int s = sb / B_, b = sb % B_;
    float v = 0.0f;
    if (d < E_) {
        v = wemb[(size_t)wid[s * B_ + b] * E_ + d];
    } else if (d < E_ + 2 * Hc_) {
        int j = d - E_;
        int n = b * S_ + s;
        v = (j < Hc_) ? (g_ch_hi[0][0][(size_t)n * Hc_ + j] + g_ch_lo[0][0][(size_t)n * Hc_ + j])
                      : (g_ch_hi[1][0][(size_t)n * Hc_ + (j - Hc_)] + g_ch_lo[1][0][(size_t)n * Hc_ + (j - Hc_)]);
    } else if (d == E_ + 2 * Hc_) {
        v = cemb[cap[s * B_ + b]];
    }
    split2(v, g_x_hi[idx], g_x_lo[idx]);
}

// ---------------- pipelined pre-split 3xTF32 GEMM ------------------------------
// C = act(A @ W^T + b1 + b2). A hi/lo (M,K), W hi/lo (N,K). M%128==0, K%16==0.
// 2-stage cp.async pipeline. Dyn smem: 2 stages x 4 arrays x 128x20 = 80 KB.
#define GE_STAGE 10240
__global__ void __launch_bounds__(256)
mma_gemm_split(const float* __restrict__ AH, const float* __restrict__ AL,
               const float* __restrict__ WH, const float* __restrict__ WL,
               const float* __restrict__ b1, const float* __restrict__ b2,
               float* __restrict__ C, float* __restrict__ Clo,
               int M, int N, int K, int act)
{
    extern __shared__ __align__(16) float sm[];
    const int tid = threadIdx.x;
    const int w = tid >> 5, l = tid & 31;
    const int wm = w & 1, wn = w >> 1;
    const int g = l >> 2, tg = l & 3;
    const int m0 = blockIdx.y * 128, n0 = blockIdx.x * 128;
    const int r = tid >> 2, c4 = (tid & 3) * 4;
    const uint32_t sbase = (uint32_t)__cvta_generic_to_shared(sm);

    float acc[4][4][4] = {};
    const int KT = K >> 4;

    // issue one k-tile's loads into a stage
    auto issue = [&](int kk, int stage) {
        uint32_t sa = sbase + (uint32_t)(stage * GE_STAGE) * 4;
#pragma unroll
        for (int h = 0; h < 2; h++) {
            int rr = r + h * 64;
            int soff = rr * 20 + c4;
            size_t aoff = (size_t)(m0 + rr) * K + kk * 16 + c4;
            cpa16(sa + (0 * 2560 + soff) * 4, &AH[aoff]);
            cpa16(sa + (1 * 2560 + soff) * 4, &AL[aoff]);
            int n = n0 + rr;
            if (n >= N) n = N - 1;   // clamp; clamped lanes never stored
            size_t woff = (size_t)n * K + kk * 16 + c4;
            cpa16(sa + (2 * 2560 + soff) * 4, &WH[woff]);
            cpa16(sa + (3 * 2560 + soff) * 4, &WL[woff]);
        }
        cpa_commit();
    };

    issue(0, 0);
    for (int kk = 0; kk < KT; kk++) {
        if (kk + 1 < KT) { issue(kk + 1, (kk + 1) & 1); cpa_wait1(); }
        else cpa_wait0();
        __syncthreads();
        const float* st = sm + (kk & 1) * GE_STAGE;
        const float* AsH = st;
        const float* AsL = st + 2560;
        const float* WsH = st + 5120;
        const float* WsL = st + 7680;
#pragma unroll
        for (int ks = 0; ks < 2; ks++) {
            unsigned ah[4][4], al[4][4], bh[4][2], bl[4][2];
#pragma unroll
            for (int mi = 0; mi < 4; mi++) {
                int rb = (wm * 64 + mi * 16 + g) * 20 + ks * 8 + tg;
                ah[mi][0] = uf(AsH[rb]);       al[mi][0] = uf(AsL[rb]);
                ah[mi][1] = uf(AsH[rb + 160]); al[mi][1] = uf(AsL[rb + 160]);
                ah[mi][2] = uf(AsH[rb + 4]);   al[mi][2] = uf(AsL[rb + 4]);
                ah[mi][3] = uf(AsH[rb + 164]); al[mi][3] = uf(AsL[rb + 164]);
            }
#pragma unroll
            for (int ni = 0; ni < 4; ni++) {
                int nb = (wn * 32 + ni * 8 + g) * 20 + ks * 8 + tg;
                bh[ni][0] = uf(WsH[nb]);     bl[ni][0] = uf(WsL[nb]);
                bh[ni][1] = uf(WsH[nb + 4]); bl[ni][1] = uf(WsL[nb + 4]);
            }
#pragma unroll
            for (int mi = 0; mi < 4; mi++)
#pragma unroll
                for (int ni = 0; ni < 4; ni++)
                    mma3(acc[mi][ni], ah[mi], al[mi], bh[ni], bl[ni]);
        }
        __syncthreads();
    }
#pragma unroll
    for (int mi = 0; mi < 4; mi++) {
#pragma unroll
        for (int ni = 0; ni < 4; ni++) {
            int m = m0 + wm * 64 + mi * 16 + g;
            int n = n0 + wn * 32 + ni * 8 + 2 * tg;
#pragma unroll
            for (int q = 0; q < 4; q++) {
                int mm = m + (q >> 1) * 8;
                int nn = n + (q & 1);
                if (nn >= N) continue;
                float v = acc[mi][ni][q];
                if (b1) v += b1[nn];
                if (b2) v += b2[nn];
                if (act == 1) v = tanhf(v);
                size_t off = (size_t)mm * N + nn;
                if (Clo) split2(v, C[off], Clo[off]);
                else C[off] = v;
            }
        }
    }
}

// ---------------- fused char LSTM step, K=128, pipelined -----------------------
// grid (4, 256, 2), block 256. tile M=64, N=128 (4 gates x 32 j), K=128.
// Dyn smem: 2 stages x 7680 floats = 60 KB. zb overlays stage area at the end.
#define CH_STAGE 7680
__global__ void __launch_bounds__(256)
char_step_kernel(const int* __restrict__ cin, int t)
{
    const int dir = blockIdx.z;
    const int t_eff = dir ? (W_ - 1 - t) : t;
    const float* hpH = g_ch_hi[dir][t & 1];
    const float* hpL = g_ch_lo[dir][t & 1];
    float* hnH = g_ch_hi[dir][(t + 1) & 1];
    float* hnL = g_ch_lo[dir][(t + 1) & 1];
    float* cst = g_char_c[dir];
    const float* WhiS = g_cwhh_hi[dir];
    const float* WloS = g_cwhh_lo[dir];
    const float* proj = g_cproj[dir];

    extern __shared__ __align__(16) float sm[];
    float (*zb)[132] = (float(*)[132])sm;
    const uint32_t sbase = (uint32_t)__cvta_generic_to_shared(sm);

    const int tid = threadIdx.x;
    const int w = tid >> 5, l = tid & 31;
    const int wm = w & 1, wn = w >> 1;
    const int g = l >> 2, tg = l & 3;
    const int j0 = blockIdx.x * 32;
    const int m0 = blockIdx.y * 64;
    const int r = tid >> 2, c4 = (tid & 3) * 4;

    float acc[2][4][4] = {};

    auto issue = [&](int kk, int stage) {
        uint32_t sa = sbase + (uint32_t)(stage * CH_STAGE) * 4;
        int k0 = kk * 16;
        {
            size_t aoff = (size_t)(m0 + r) * Hc_ + k0 + c4;
            int soff = r * 20 + c4;
            cpa16(sa + (0 + soff) * 4, &hpH[aoff]);
            cpa16(sa + (1280 + soff) * 4, &hpL[aoff]);
        }
#pragma unroll
        for (int h = 0; h < 2; h++) {
            int rr = r + h * 64;
            int wr = (rr >> 5) * Hc_ + j0 + (rr & 31);
            size_t woff = (size_t)wr * Hc_ + k0 + c4;
            int soff = rr * 20 + c4;
            cpa16(sa + (2560 + soff) * 4, &WhiS[woff]);
            cpa16(sa + (5120 + soff) * 4, &WloS[woff]);
        }
        cpa_commit();
    };

    issue(0, 0);
#pragma unroll 1
    for (int kk = 0; kk < 8; kk++) {
        if (kk + 1 < 8) { issue(kk + 1, (kk + 1) & 1); cpa_wait1(); }
        else cpa_wait0();
        __syncthreads();
        const float* st = sm + (kk & 1) * CH_STAGE;
        const float* AsH = st;
        const float* AsL = st + 1280;
        const float* WsH = st + 2560;
        const float* WsL = st + 5120;
#pragma unroll
        for (int ks = 0; ks < 2; ks++) {
            unsigned ah[2][4], al[2][4], bh[4][2], bl[4][2];
#pragma unroll
            for (int mi = 0; mi < 2; mi++) {
                int rb = (wm * 32 + mi * 16 + g) * 20 + ks * 8 + tg;
                ah[mi][0] = uf(AsH[rb]);       al[mi][0] = uf(AsL[rb]);
                ah[mi][1] = uf(AsH[rb + 160]); al[mi][1] = uf(AsL[rb + 160]);
                ah[mi][2] = uf(AsH[rb + 4]);   al[mi][2] = uf(AsL[rb + 4]);
                ah[mi][3] = uf(AsH[rb + 164]); al[mi][3] = uf(AsL[rb + 164]);
            }
#pragma unroll
            for (int ni = 0; ni < 4; ni++) {
                int nb = (wn * 32 + ni * 8 + g) * 20 + ks * 8 + tg;
                bh[ni][0] = uf(WsH[nb]);     bl[ni][0] = uf(WsL[nb]);
                bh[ni][1] = uf(WsH[nb + 4]); bl[ni][1] = uf(WsL[nb + 4]);
            }
#pragma unroll
            for (int mi = 0; mi < 2; mi++)
#pragma unroll
                for (int ni = 0; ni < 4; ni++)
                    mma3(acc[mi][ni], ah[mi], al[mi], bh[ni], bl[ni]);
        }
        __syncthreads();
    }
    // stage z (overlays stages; all mma reads done)
#pragma unroll
    for (int mi = 0; mi < 2; mi++) {
#pragma unroll
        for (int ni = 0; ni < 4; ni++) {
            int row = wm * 32 + mi * 16 + g;
            int col = wn * 32 + ni * 8 + 2 * tg;
            zb[row][col]         = acc[mi][ni][0];
            zb[row][col + 1]     = acc[mi][ni][1];
            zb[row + 8][col]     = acc[mi][ni][2];
            zb[row + 8][col + 1] = acc[mi][ni][3];
        }
    }
    __syncthreads();
    for (int idx = tid; idx < 64 * 32; idx += 256) {
        int ml = idx >> 5, jj = idx & 31;
        int j = j0 + jj;
        int m = m0 + ml;
        int cid = cin[m * W_ + t_eff];
        const float* pr = &proj[(size_t)cid * 4 * Hc_];
        float zi = zb[ml][jj]      + pr[j];
        float zf = zb[ml][32 + jj] + pr[Hc_ + j];
        float zg = zb[ml][64 + jj] + pr[2 * Hc_ + j];
        float zo = zb[ml][96 + jj] + pr[3 * Hc_ + j];
        size_t off = (size_t)m * Hc_ + j;
        float c = cst[off];
        c = sigf(zf) * c + sigf(zi) * tanhf(zg);
        cst[off] = c;
        float hv = sigf(zo) * tanhf(c);
        split2(hv, hnH[off], hnL[off]);
    }
}

// ---------------- persistent word BiLSTM (pipelined A) ---------------------------
// 128 blocks (64/dir), 256 thr. Weights cached split in smem for all 256 steps.
// A (h) double-buffered via cp.async. Grid barrier per dir per step.
#define WP_W    (2 * 32 * 516)          // 33024
#define WP_AST  (2 * 64 * 68)           // 8704 per stage
#define WP_ZB   (64 * 36)               // 2304
#define WP_SMEM_FLOATS (WP_W + 2 * WP_AST + WP_ZB)
__device__ __forceinline__ void grid_bar_dir(int dir) {
    __syncthreads();
    if (threadIdx.x == 0) {
        __threadfence();
        int gen = g_bar_gen[dir];
        if (atomicAdd((int*)&g_bar_count[dir], 1) == 63) {
            g_bar_count[dir] = 0;
            __threadfence();
            g_bar_gen[dir] = gen + 1;
        } else {
            while (g_bar_gen[dir] == gen) __nanosleep(20);
            __threadfence();
        }
    }
    __syncthreads();
}

__global__ void __launch_bounds__(256)
word_persistent(const float* __restrict__ WhhF, const float* __restrict__ WhhB)
{
    extern __shared__ float sm[];
    float* WH = sm;                       // 32 x 516
    float* WL = sm + 32 * 516;
    float* zbf = sm + WP_W + 2 * WP_AST;
    float (*zb)[36] = (float(*)[36])zbf;
    const uint32_t sbase = (uint32_t)__cvta_generic_to_shared(sm);

    const int dir = blockIdx.x >> 6;
    const int jb = blockIdx.x & 63;
    const int j0 = jb * 8;
    const int tid = threadIdx.x;
    const int w = tid >> 5, l = tid & 31;
    const int wm = w & 3, wn = w >> 2;
    const int g = l >> 2, tg = l & 3;

    const float* Whh = dir ? WhhB : WhhF;
    for (int i = tid; i < 32 * 512; i += 256) {
        int rr = i >> 9, k = i & 511;
        int wr = (rr >> 3) * Hw_ + j0 + (rr & 7);
        split2(Whh[(size_t)wr * Hw_ + k], WH[rr * 516 + k], WL[rr * 516 + k]);
    }
    __syncthreads();

    const float* xbase = g_wxproj[dir];
    float* cst = g_word_c[dir];

    for (int t = 0; t < S_; t++) {
        const int s = dir ? (S_ - 1 - t) : t;
        const float* hpH = g_wh_hi[dir][t & 1];
        const float* hpL = g_wh_lo[dir][t & 1];
        float* hnH = g_wh_hi[dir][(t + 1) & 1];
        float* hnL = g_wh_lo[dir][(t + 1) & 1];

        auto issueA = [&](int ko, int stage) {
            uint32_t sa = sbase + (uint32_t)(WP_W + stage * WP_AST) * 4;
#pragma unroll
            for (int q = 0; q < 4; q++) {
                int idx = tid + q * 256;
                int row = idx >> 4, col = (idx & 15) * 4;
                size_t goff = (size_t)row * Hw_ + ko * 64 + col;
                int soff = row * 68 + col;
                cpa16(sa + soff * 4, &hpH[goff]);
                cpa16(sa + (4352 + soff) * 4, &hpL[goff]);
            }
            cpa_commit();
        };

        float acc[2][4] = {};
        issueA(0, 0);
#pragma unroll 1
        for (int ko = 0; ko < 8; ko++) {
            if (ko + 1 < 8) { issueA(ko + 1, (ko + 1) & 1); cpa_wait1(); }
            else cpa_wait0();
            __syncthreads();
            const float* AH = sm + WP_W + (ko & 1) * WP_AST;
            const float* AL = AH + 4352;
#pragma unroll
            for (int k8 = 0; k8 < 8; k8++) {
                int kc = k8 * 8;
                unsigned ah[4], al[4];
                int rb = (wm * 16 + g) * 68 + kc + tg;
                ah[0] = uf(AH[rb]);              al[0] = uf(AL[rb]);
                ah[1] = uf(AH[rb + 8 * 68]);     al[1] = uf(AL[rb + 8 * 68]);
                ah[2] = uf(AH[rb + 4]);          al[2] = uf(AL[rb + 4]);
                ah[3] = uf(AH[rb + 8 * 68 + 4]); al[3] = uf(AL[rb + 8 * 68 + 4]);
#pragma unroll
                for (int ni = 0; ni < 2; ni++) {
                    int nb = (wn * 16 + ni * 8 + g) * 516 + ko * 64 + kc + tg;
                    unsigned bh[2], bl[2];
                    bh[0] = uf(WH[nb]);     bl[0] = uf(WL[nb]);
                    bh[1] = uf(WH[nb + 4]); bl[1] = uf(WL[nb + 4]);
                    mma3(acc[ni], ah, al, bh, bl);
                }
            }
            __syncthreads();
        }
#pragma unroll
        for (int ni = 0; ni < 2; ni++) {
            int row = wm * 16 + g;
            int col = wn * 16 + ni * 8 + 2 * tg;
            zb[row][col]         = acc[ni][0];
            zb[row][col + 1]     = acc[ni][1];
            zb[row + 8][col]     = acc[ni][2];
            zb[row + 8][col + 1] = acc[ni][3];
        }
        __syncthreads();
        for (int idx = tid; idx < 512; idx += 256) {
            int b = idx >> 3, jj = idx & 7;
            int j = j0 + jj;
            const float* xr = xbase + ((size_t)s * B_ + b) * 4 * Hw_;
            float zi = zb[b][jj]      + xr[j];
            float zf = zb[b][8 + jj]  + xr[Hw_ + j];
            float zg = zb[b][16 + jj] + xr[2 * Hw_ + j];
            float zo = zb[b][24 + jj] + xr[3 * Hw_ + j];
            size_t off = (size_t)b * Hw_ + j;
            float c = cst[off];
            c = sigf(zf) * c + sigf(zi) * tanhf(zg);
            cst[off] = c;
            float hv = sigf(zo) * tanhf(c);
            float hh, hl;
            split2(hv, hh, hl);
            hnH[off] = hh; hnL[off] = hl;
            size_t eoff = ((size_t)s * B_ + b) * (2 * Hw_) + dir * Hw_ + j;
            g_enc_hi[eoff] = hh; g_enc_lo[eoff] = hl;
        }
        grid_bar_dir(dir);
    }
}

// ---------------- CRF forward (logZ per batch) ----------------
__global__ void __launch_bounds__(32)
crf_alpha_kernel(const float* __restrict__ trans, const float* __restrict__ start,
                 const float* __restrict__ endv)
{
    __shared__ float tr[T_][T_];
    __shared__ float alpha[T_];
    const int b = blockIdx.x;
    const int to = threadIdx.x;
    for (int i = to; i < T_ * T_; i += T_) tr[i / T_][i % T_] = trans[i];
    alpha[to] = start[to] + g_logits[(size_t)(0 * B_ + b) * T_ + to];
    __syncthreads();
    for (int s = 1; s < S_; s++) {
        float m = -1e30f;
#pragma unroll
        for (int f = 0; f < T_; f++) m = fmaxf(m, alpha[f] + tr[f][to]);
        float sum = 0.0f;
#pragma unroll
        for (int f = 0; f < T_; f++) sum += expf(alpha[f] + tr[f][to] - m);
        float a = m + logf(sum) + g_logits[((size_t)s * B_ + b) * T_ + to];
        __syncthreads();
        alpha[to] = a;
        __syncthreads();
    }
    float v = alpha[to] + endv[to];
    float m = v;
#pragma unroll
    for (int o = 16; o > 0; o >>= 1) m = fmaxf(m, __shfl_xor_sync(0xffffffffu, m, o));
    float e = expf(v - m);
#pragma unroll
    for (int o = 16; o > 0; o >>= 1) e += __shfl_xor_sync(0xffffffffu, e, o);
    if (to == 0) g_logZ[b] = m + logf(e);
}

// ---------------- CRF gold score + loss ----------------
__global__ void __launch_bounds__(64)
crf_loss_kernel(const int* __restrict__ tags, const float* __restrict__ trans,
                const float* __restrict__ start, const float* __restrict__ endv,
                float* __restrict__ out, int out_size)
{
    __shared__ float red[B_];
    const int b = threadIdx.x;
    int prev = tags[0 * B_ + b];
    float score = start[prev];
    for (int s = 0; s < S_; s++) {
        int tg = tags[s * B_ + b];
        score += g_logits[((size_t)s * B_ + b) * T_ + tg];
        if (s > 0) score += trans[prev * T_ + tg];
        prev = tg;
    }
    score += endv[prev];
    red[b] = g_logZ[b] - score;
    __syncthreads();
    if (b == 0) {
        float t = 0.0f;
        for (int i = 0; i < B_; i++) t += red[i];
        if (out_size > 0) out[0] = t;
    }
}

// ---------------- Viterbi decode ----------------
__global__ void __launch_bounds__(32)
viterbi_kernel(const float* __restrict__ trans, const float* __restrict__ start,
               const float* __restrict__ endv, float* __restrict__ out, int out_size)
{
    __shared__ float tr[T_][T_];
    __shared__ float v[T_];
    __shared__ unsigned char bp[S_ - 1][T_];
    const int b = blockIdx.x;
    const int to = threadIdx.x;
    for (int i = to; i < T_ * T_; i += T_) tr[i / T_][i % T_] = trans[i];
    v[to] = start[to] + g_logits[(size_t)b * T_ + to];
    __syncthreads();
    for (int s = 1; s < S_; s++) {
        float best = -1e30f;
        int arg = 0;
#pragma unroll
        for (int f = 0; f < T_; f++) {
            float sc = v[f] + tr[f][to];
            if (sc > best) { best = sc; arg = f; }
        }
        bp[s - 1][to] = (unsigned char)arg;
        float nv = best + g_logits[((size_t)s * B_ + b) * T_ + to];
        __syncthreads();
        v[to] = nv;
        __syncthreads();
    }
    if (to == 0) {
        float best = -1e30f;
        int last = 0;
        for (int f = 0; f < T_; f++) {
            float sc = v[f] + endv[f];
            if (sc > best) { best = sc; last = f; }
        }
        int tag = last;
        int base = 1 + b * S_;
        if (base + S_ - 1 < out_size) out[base + S_ - 1] = (float)tag;
        for (int s = S_ - 2; s >= 0; s--) {
            tag = bp[s][tag];
            if (base + s < out_size) out[base + s] = (float)tag;
        }
    }
}

// ---------------- host-side orchestration ----------------
extern "C" void kernel_launch(void* const* d_in, const int* in_sizes, int n_in,
                              void* d_out, int out_size) {
    (void)in_sizes; (void)n_in;
    const int*   word_inputs = (const int*)d_in[0];
    const int*   char_inputs = (const int*)d_in[1];
    const int*   cap_inputs  = (const int*)d_in[2];
    const int*   tag_inputs  = (const int*)d_in[3];
    const float* word_emb    = (const float*)d_in[4];
    const float* cap_emb     = (const float*)d_in[5];
    const float* char_emb    = (const float*)d_in[6];
    const float* cWih_f = (const float*)d_in[7];
    const float* cWhh_f = (const float*)d_in[8];
    const float* cbih_f = (const float*)d_in[9];
    const float* cbhh_f = (const float*)d_in[10];
    const float* cWih_b = (const float*)d_in[11];
    const float* cWhh_b = (const float*)d_in[12];
    const float* cbih_b = (const float*)d_in[13];
    const float* cbhh_b = (const float*)d_in[14];
    const float* wWih_f = (const float*)d_in[15];
    const float* wWhh_f = (const float*)d_in[16];
    const float* wbih_f = (const float*)d_in[17];
    const float* wbhh_f = (const float*)d_in[18];
    const float* wWih_b = (const float*)d_in[19];
    const float* wWhh_b = (const float*)d_in[20];
    const float* wbih_b = (const float*)d_in[21];
    const float* wbhh_b = (const float*)d_in[22];
    const float* ff1_W  = (const float*)d_in[23];
    const float* ff1_b  = (const float*)d_in[24];
    const float* ff2_W  = (const float*)d_in[25];
    const float* ff2_b  = (const float*)d_in[26];
    const float* trans  = (const float*)d_in[27];
    const float* start_trans = (const float*)d_in[28];
    const float* end_trans   = (const float*)d_in[29];
    float* out = (float*)d_out;

    float *pxh, *pxl, *pwih_h, *pwih_l, *pwx, *pench, *pencl, *ph1h, *ph1l, *plog;
    float *pcwhh_h, *pcwhh_l, *pff1h, *pff1l, *pff2h, *pff2l;
    cudaGetSymbolAddress((void**)&pxh,     g_x_hi);
    cudaGetSymbolAddress((void**)&pxl,     g_x_lo);
    cudaGetSymbolAddress((void**)&pwih_h,  g_wih_hi);
    cudaGetSymbolAddress((void**)&pwih_l,  g_wih_lo);
    cudaGetSymbolAddress((void**)&pwx,     g_wxproj);
    cudaGetSymbolAddress((void**)&pench,   g_enc_hi);
    cudaGetSymbolAddress((void**)&pencl,   g_enc_lo);
    cudaGetSymbolAddress((void**)&ph1h,    g_h1_hi);
    cudaGetSymbolAddress((void**)&ph1l,    g_h1_lo);
    cudaGetSymbolAddress((void**)&plog,    g_logits);
    cudaGetSymbolAddress((void**)&pcwhh_h, g_cwhh_hi);
    cudaGetSymbolAddress((void**)&pcwhh_l, g_cwhh_lo);
    cudaGetSymbolAddress((void**)&pff1h,   g_ff1w_hi);
    cudaGetSymbolAddress((void**)&pff1l,   g_ff1w_lo);
    cudaGetSymbolAddress((void**)&pff2h,   g_ff2w_hi);
    cudaGetSymbolAddress((void**)&pff2l,   g_ff2w_lo);

    const size_t wih_per = (size_t)4 * Hw_ * Kp_;
    const size_t wx_per = (size_t)NC_ * 4 * Hw_;
    const int cwhh_n = 4 * Hc_ * Hc_;

    const int ge_smem = 2 * GE_STAGE * (int)sizeof(float);   // 80 KB
    const int ch_smem = 2 * CH_STAGE * (int)sizeof(float);   // 60 KB
    const int wp_smem = WP_SMEM_FLOATS * (int)sizeof(float); // ~206 KB
    cudaFuncSetAttribute(mma_gemm_split, cudaFuncAttributeMaxDynamicSharedMemorySize, ge_smem);
    cudaFuncSetAttribute(char_step_kernel, cudaFuncAttributeMaxDynamicSharedMemorySize, ch_smem);
    cudaFuncSetAttribute(word_persistent, cudaFuncAttributeMaxDynamicSharedMemorySize, wp_smem);

    // 0) init + weight prep
    zero_out_kernel<<<512, 256>>>(out, out_size);
    zero_state_kernel<<<2048, 256>>>();
    pad_split_wih<<<(int)((2 * wih_per + 255) / 256), 256>>>(wWih_f, wWih_b);
    split_arr_kernel<<<(cwhh_n + 255) / 256, 256>>>(cWhh_f, pcwhh_h, pcwhh_l, cwhh_n);
    split_arr_kernel<<<(cwhh_n + 255) / 256, 256>>>(cWhh_b, pcwhh_h + cwhh_n, pcwhh_l + cwhh_n, cwhh_n);
    split_arr_kernel<<<(Hw_ * 2 * Hw_ + 255) / 256, 256>>>(ff1_W, pff1h, pff1l, Hw_ * 2 * Hw_);
    split_arr_kernel<<<(T_ * Hw_ + 255) / 256, 256>>>(ff2_W, pff2h, pff2l, T_ * Hw_);
    char_vocab_proj<<<2 * VC_, 256>>>(char_emb, cWih_f, cbih_f, cbhh_f, cWih_b, cbih_b, cbhh_b);

    // 1) char BiLSTM (fused, pipelined, K=128)
    for (int t = 0; t < W_; t++)
        char_step_kernel<<<dim3(4, NC_ / 64, 2), 256, ch_smem>>>(char_inputs, t);

    // 2) build padded + split word input
    build_x_kernel<<<(NC_ * Kp_ + 255) / 256, 256>>>(word_inputs, cap_inputs, word_emb, cap_emb);

    // 3) word input projections
    mma_gemm_split<<<dim3(4 * Hw_ / 128, NC_ / 128), 256, ge_smem>>>(
        pxh, pxl, pwih_h, pwih_l, wbih_f, wbhh_f, pwx, nullptr, NC_, 4 * Hw_, Kp_, 0);
    mma_gemm_split<<<dim3(4 * Hw_ / 128, NC_ / 128), 256, ge_smem>>>(
        pxh, pxl, pwih_h + wih_per, pwih_l + wih_per, wbih_b, wbhh_b,
        pwx + wx_per, nullptr, NC_, 4 * Hw_, Kp_, 0);

    // 4) persistent word BiLSTM
    word_persistent<<<128, 256, wp_smem>>>(wWhh_f, wWhh_b);

    // 5) feed-forward head
    mma_gemm_split<<<dim3(Hw_ / 128, NC_ / 128), 256, ge_smem>>>(
        pench, pencl, pff1h, pff1l, ff1_b, nullptr, ph1h, ph1l, NC_, Hw_, 2 * Hw_, 1);
    mma_gemm_split<<<dim3(1, NC_ / 128), 256, ge_smem>>>(
        ph1h, ph1l, pff2h, pff2l, ff2_b, nullptr, plog, nullptr, NC_, T_, Hw_, 0);

    // 6) CRF loss + Viterbi
    crf_alpha_kernel<<<B_, T_>>>(trans, start_trans, end_trans);
    crf_loss_kernel<<<1, B_>>>(tag_inputs, trans, start_trans, end_trans, out, out_size);
    viterbi_kernel<<<B_, T_>>>(trans, start_trans, end_trans, out, out_size);
}

// round 7
// speedup vs baseline: 2.5213x; 1.0035x over previous
#include <cuda_runtime.h>
#include <stdint.h>
#include <math.h>

// ---------------- problem constants ----------------
#define S_   256
#define B_   64
#define W_   16
#define Ec_  64
#define Hc_  128
#define E_   300
#define Hw_  512
#define T_   32
#define D_   557           // 1 + E + 2*Hc
#define Kp_  576           // D padded to multiple of 16
#define NC_  (B_ * S_)     // 16384 words for char encoder
#define VC_  128           // char vocab

// ---------------- scratch (device globals; no allocs allowed) ----------------
__device__ float g_ch_hi[2][2][NC_ * Hc_];     // char h, tf32-hi, [dir][buf]
__device__ float g_ch_lo[2][2][NC_ * Hc_];     // char h, tf32-lo
__device__ float g_char_c[2][NC_ * Hc_];
__device__ float g_cproj[2][VC_ * 4 * Hc_];    // per-vocab emb@Wih^T + biases
__device__ float g_cwhh_hi[2][4 * Hc_ * Hc_];
__device__ float g_cwhh_lo[2][4 * Hc_ * Hc_];
__device__ float g_x_hi[NC_ * Kp_];
__device__ float g_x_lo[NC_ * Kp_];
__device__ float g_wih_hi[2][4 * Hw_ * Kp_];   // padded word Wih split
__device__ float g_wih_lo[2][4 * Hw_ * Kp_];
__device__ float g_wxproj[2][(size_t)NC_ * 4 * Hw_];
__device__ float g_wh_hi[2][2][B_ * Hw_];
__device__ float g_wh_lo[2][2][B_ * Hw_];
__device__ float g_word_c[2][B_ * Hw_];
__device__ float g_enc_hi[(size_t)NC_ * 2 * Hw_];
__device__ float g_enc_lo[(size_t)NC_ * 2 * Hw_];
__device__ float g_h1_hi[(size_t)NC_ * Hw_];
__device__ float g_h1_lo[(size_t)NC_ * Hw_];
__device__ float g_ff1w_hi[Hw_ * 2 * Hw_];
__device__ float g_ff1w_lo[Hw_ * 2 * Hw_];
__device__ float g_ff2w_hi[T_ * Hw_];
__device__ float g_ff2w_lo[T_ * Hw_];
__device__ float g_logits[NC_ * T_];
__device__ float g_logZ[B_];
__device__ volatile int g_bar_count[2];
__device__ volatile int g_bar_gen[2];

__device__ __forceinline__ float sigf(float x) { return 1.0f / (1.0f + expf(-x)); }

__device__ __forceinline__ unsigned f2tf(float f) {
    unsigned u;
    asm("cvt.rna.tf32.f32 %0, %1;" : "=r"(u) : "f"(f));
    return u;
}
__device__ __forceinline__ float fu(unsigned u) { return __uint_as_float(u); }
__device__ __forceinline__ unsigned uf(float f) { return __float_as_uint(f); }
__device__ __forceinline__ void split2(float v, float& hi, float& lo) {
    unsigned h = f2tf(v);
    hi = fu(h);
    lo = fu(f2tf(v - fu(h)));
}

__device__ __forceinline__ void mma8(float* c, const unsigned* a, const unsigned* b) {
    asm volatile(
        "mma.sync.aligned.m16n8k8.row.col.f32.tf32.tf32.f32 "
        "{%0,%1,%2,%3}, {%4,%5,%6,%7}, {%8,%9}, {%0,%1,%2,%3};"
        : "+f"(c[0]), "+f"(c[1]), "+f"(c[2]), "+f"(c[3])
        : "r"(a[0]), "r"(a[1]), "r"(a[2]), "r"(a[3]), "r"(b[0]), "r"(b[1]));
}
__device__ __forceinline__ void mma3(float* c, const unsigned* ah, const unsigned* al,
                                     const unsigned* bh, const unsigned* bl) {
    mma8(c, al, bh);
    mma8(c, ah, bl);
    mma8(c, ah, bh);
}

// cp.async helpers
__device__ __forceinline__ void cpa16(uint32_t saddr, const void* gptr) {
    asm volatile("cp.async.ca.shared.global [%0], [%1], 16;" :: "r"(saddr), "l"(gptr));
}
__device__ __forceinline__ void cpa_commit() {
    asm volatile("cp.async.commit_group;");
}
__device__ __forceinline__ void cpa_wait0() {
    asm volatile("cp.async.wait_group 0;");
}

// ---------------- merged prep kernel (1 launch) ----------------
__global__ void __launch_bounds__(256)
prep_kernel(float* __restrict__ out, int out_size,
            const float* __restrict__ wWf, const float* __restrict__ wWb,
            const float* __restrict__ cWhhF, const float* __restrict__ cWhhB,
            const float* __restrict__ ff1W, const float* __restrict__ ff2W)
{
    const int stride = gridDim.x * blockDim.x;
    const int i0 = blockIdx.x * blockDim.x + threadIdx.x;
    for (int i = i0; i < out_size; i += stride) out[i] = 0.0f;
    for (int i = i0; i < 2 * 2 * NC_ * Hc_; i += stride) {
        (&g_ch_hi[0][0][0])[i] = 0.0f;
        (&g_ch_lo[0][0][0])[i] = 0.0f;
    }
    for (int i = i0; i < 2 * NC_ * Hc_; i += stride)
        (&g_char_c[0][0])[i] = 0.0f;
    for (int i = i0; i < 2 * 2 * B_ * Hw_; i += stride) {
        (&g_wh_hi[0][0][0])[i] = 0.0f;
        (&g_wh_lo[0][0][0])[i] = 0.0f;
    }
    for (int i = i0; i < 2 * B_ * Hw_; i += stride)
        (&g_word_c[0][0])[i] = 0.0f;
    // pad + split word Wih
    const int per = 4 * Hw_ * Kp_;
    for (int idx = i0; idx < 2 * per; idx += stride) {
        int dir = idx / per;
        int r = idx - dir * per;
        int n = r / Kp_, k = r - n * Kp_;
        const float* Wsrc = dir ? wWb : wWf;
        float v = (k < D_) ? Wsrc[(size_t)n * D_ + k] : 0.0f;
        split2(v, g_wih_hi[dir][r], g_wih_lo[dir][r]);
    }
    // split char Whh
    const int cn = 4 * Hc_ * Hc_;
    for (int i = i0; i < cn; i += stride) {
        split2(cWhhF[i], g_cwhh_hi[0][i], g_cwhh_lo[0][i]);
        split2(cWhhB[i], g_cwhh_hi[1][i], g_cwhh_lo[1][i]);
    }
    // split ff weights
    for (int i = i0; i < Hw_ * 2 * Hw_; i += stride)
        split2(ff1W[i], g_ff1w_hi[i], g_ff1w_lo[i]);
    for (int i = i0; i < T_ * Hw_; i += stride)
        split2(ff2W[i], g_ff2w_hi[i], g_ff2w_lo[i]);
}

__global__ void __launch_bounds__(256)
char_vocab_proj(const float* __restrict__ emb,
                const float* __restrict__ WihF, const float* __restrict__ bihF,
                const float* __restrict__ bhhF,
                const float* __restrict__ WihB, const float* __restrict__ bihB,
                const float* __restrict__ bhhB)
{
    int dir = blockIdx.x >> 7;
    int cid = blockIdx.x & 127;
    const float* Wih = dir ? WihB : WihF;
    const float* bih = dir ? bihB : bihF;
    const float* bhh = dir ? bhhB : bhhF;
    __shared__ float e[Ec_];
    if (threadIdx.x < Ec_) e[threadIdx.x] = emb[cid * Ec_ + threadIdx.x];
    __syncthreads();
    for (int n = threadIdx.x; n < 4 * Hc_; n += 256) {
        float s = bih[n] + bhh[n];
        const float* wr = &Wih[(size_t)n * Ec_];
#pragma unroll 8
        for (int k = 0; k < Ec_; k++) s += e[k] * wr[k];
        g_cproj[dir][cid * 4 * Hc_ + n] = s;
    }
}

__global__ void __launch_bounds__(256)
build_x_kernel(const int* __restrict__ wid, const int* __restrict__ cap,
               const float* __restrict__ wemb, const float* __restrict__ cemb)
{
    int idx = blockIdx.x * blockDim.x + threadIdx.x;
    if (idx >= NC_ * Kp_) return;
    int d = idx % Kp_;
    int sb = idx / Kp_;
    int s = sb / B_, b = sb % B_;
    float v = 0.0f;
    if (d < E_) {
        v = wemb[(size_t)wid[s * B_ + b] * E_ + d];
    } else if (d < E_ + 2 * Hc_) {
        int j = d - E_;
        int n = b * S_ + s;
        v = (j < Hc_) ? (g_ch_hi[0][0][(size_t)n * Hc_ + j] + g_ch_lo[0][0][(size_t)n * Hc_ + j])
                      : (g_ch_hi[1][0][(size_t)n * Hc_ + (j - Hc_)] + g_ch_lo[1][0][(size_t)n * Hc_ + (j - Hc_)]);
    } else if (d == E_ + 2 * Hc_) {
        v = cemb[cap[s * B_ + b]];
    }
    split2(v, g_x_hi[idx], g_x_lo[idx]);
}

// ---------------- pipelined pre-split 3xTF32 GEMM (single sync / k-tile) -------
// C = act(A @ W^T + b1 + b2). A hi/lo (M,K), W hi/lo (N,K). M%128==0, K%16==0.
#define GE_STAGE 10240
__global__ void __launch_bounds__(256)
mma_gemm_split(const float* __restrict__ AH, const float* __restrict__ AL,
               const float* __restrict__ WH, const float* __restrict__ WL,
               const float* __restrict__ b1, const float* __restrict__ b2,
               float* __restrict__ C, float* __restrict__ Clo,
               int M, int N, int K, int act)
{
    extern __shared__ __align__(16) float sm[];
    const int tid = threadIdx.x;
    const int w = tid >> 5, l = tid & 31;
    const int wm = w & 1, wn = w >> 1;
    const int g = l >> 2, tg = l & 3;
    const int m0 = blockIdx.y * 128, n0 = blockIdx.x * 128;
    const int r = tid >> 2, c4 = (tid & 3) * 4;
    const uint32_t sbase = (uint32_t)__cvta_generic_to_shared(sm);

    float acc[4][4][4] = {};
    const int KT = K >> 4;

    auto issue = [&](int kk, int stage) {
        uint32_t sa = sbase + (uint32_t)(stage * GE_STAGE) * 4;
#pragma unroll
        for (int h = 0; h < 2; h++) {
            int rr = r + h * 64;
            int soff = rr * 20 + c4;
            size_t aoff = (size_t)(m0 + rr) * K + kk * 16 + c4;
            cpa16(sa + (0 * 2560 + soff) * 4, &AH[aoff]);
            cpa16(sa + (1 * 2560 + soff) * 4, &AL[aoff]);
            int n = n0 + rr;
            if (n >= N) n = N - 1;   // clamp; clamped lanes never stored
            size_t woff = (size_t)n * K + kk * 16 + c4;
            cpa16(sa + (2 * 2560 + soff) * 4, &WH[woff]);
            cpa16(sa + (3 * 2560 + soff) * 4, &WL[woff]);
        }
        cpa_commit();
    };

    issue(0, 0);
    for (int kk = 0; kk < KT; kk++) {
        cpa_wait0();
        __syncthreads();
        if (kk + 1 < KT) issue(kk + 1, (kk + 1) & 1);
        const float* st = sm + (kk & 1) * GE_STAGE;
        const float* AsH = st;
        const float* AsL = st + 2560;
        const float* WsH = st + 5120;
        const float* WsL = st + 7680;
#pragma unroll
        for (int ks = 0; ks < 2; ks++) {
            unsigned ah[4][4], al[4][4], bh[4][2], bl[4][2];
#pragma unroll
            for (int mi = 0; mi < 4; mi++) {
                int rb = (wm * 64 + mi * 16 + g) * 20 + ks * 8 + tg;
                ah[mi][0] = uf(AsH[rb]);       al[mi][0] = uf(AsL[rb]);
                ah[mi][1] = uf(AsH[rb + 160]); al[mi][1] = uf(AsL[rb + 160]);
                ah[mi][2] = uf(AsH[rb + 4]);   al[mi][2] = uf(AsL[rb + 4]);
                ah[mi][3] = uf(AsH[rb + 164]); al[mi][3] = uf(AsL[rb + 164]);
            }
#pragma unroll
            for (int ni = 0; ni < 4; ni++) {
                int nb = (wn * 32 + ni * 8 + g) * 20 + ks * 8 + tg;
                bh[ni][0] = uf(WsH[nb]);     bl[ni][0] = uf(WsL[nb]);
                bh[ni][1] = uf(WsH[nb + 4]); bl[ni][1] = uf(WsL[nb + 4]);
            }
#pragma unroll
            for (int mi = 0; mi < 4; mi++)
#pragma unroll
                for (int ni = 0; ni < 4; ni++)
                    mma3(acc[mi][ni], ah[mi], al[mi], bh[ni], bl[ni]);
        }
    }
#pragma unroll
    for (int mi = 0; mi < 4; mi++) {
#pragma unroll
        for (int ni = 0; ni < 4; ni++) {
            int m = m0 + wm * 64 + mi * 16 + g;
            int n = n0 + wn * 32 + ni * 8 + 2 * tg;
#pragma unroll
            for (int q = 0; q < 4; q++) {
                int mm = m + (q >> 1) * 8;
                int nn = n + (q & 1);
                if (nn >= N) continue;
                float v = acc[mi][ni][q];
                if (b1) v += b1[nn];
                if (b2) v += b2[nn];
                if (act == 1) v = tanhf(v);
                size_t off = (size_t)mm * N + nn;
                if (Clo) split2(v, C[off], Clo[off]);
                else C[off] = v;
            }
        }
    }
}

// ---------------- fused char LSTM step, K=128, single-sync pipeline ------------
#define CH_STAGE 7680
__global__ void __launch_bounds__(256)
char_step_kernel(const int* __restrict__ cin, int t)
{
    const int dir = blockIdx.z;
    const int t_eff = dir ? (W_ - 1 - t) : t;
    const float* hpH = g_ch_hi[dir][t & 1];
    const float* hpL = g_ch_lo[dir][t & 1];
    float* hnH = g_ch_hi[dir][(t + 1) & 1];
    float* hnL = g_ch_lo[dir][(t + 1) & 1];
    float* cst = g_char_c[dir];
    const float* WhiS = g_cwhh_hi[dir];
    const float* WloS = g_cwhh_lo[dir];
    const float* proj = g_cproj[dir];

    extern __shared__ __align__(16) float sm[];
    float (*zb)[132] = (float(*)[132])sm;
    const uint32_t sbase = (uint32_t)__cvta_generic_to_shared(sm);

    const int tid = threadIdx.x;
    const int w = tid >> 5, l = tid & 31;
    const int wm = w & 1, wn = w >> 1;
    const int g = l >> 2, tg = l & 3;
    const int j0 = blockIdx.x * 32;
    const int m0 = blockIdx.y * 64;
    const int r = tid >> 2, c4 = (tid & 3) * 4;

    float acc[2][4][4] = {};

    auto issue = [&](int kk, int stage) {
        uint32_t sa = sbase + (uint32_t)(stage * CH_STAGE) * 4;
        int k0 = kk * 16;
        {
            size_t aoff = (size_t)(m0 + r) * Hc_ + k0 + c4;
            int soff = r * 20 + c4;
            cpa16(sa + (0 + soff) * 4, &hpH[aoff]);
            cpa16(sa + (1280 + soff) * 4, &hpL[aoff]);
        }
#pragma unroll
        for (int h = 0; h < 2; h++) {
            int rr = r + h * 64;
            int wr = (rr >> 5) * Hc_ + j0 + (rr & 31);
            size_t woff = (size_t)wr * Hc_ + k0 + c4;
            int soff = rr * 20 + c4;
            cpa16(sa + (2560 + soff) * 4, &WhiS[woff]);
            cpa16(sa + (5120 + soff) * 4, &WloS[woff]);
        }
        cpa_commit();
    };

    issue(0, 0);
#pragma unroll 1
    for (int kk = 0; kk < 8; kk++) {
        cpa_wait0();
        __syncthreads();
        if (kk + 1 < 8) issue(kk + 1, (kk + 1) & 1);
        const float* st = sm + (kk & 1) * CH_STAGE;
        const float* AsH = st;
        const float* AsL = st + 1280;
        const float* WsH = st + 2560;
        const float* WsL = st + 5120;
#pragma unroll
        for (int ks = 0; ks < 2; ks++) {
            unsigned ah[2][4], al[2][4], bh[4][2], bl[4][2];
#pragma unroll
            for (int mi = 0; mi < 2; mi++) {
                int rb = (wm * 32 + mi * 16 + g) * 20 + ks * 8 + tg;
                ah[mi][0] = uf(AsH[rb]);       al[mi][0] = uf(AsL[rb]);
                ah[mi][1] = uf(AsH[rb + 160]); al[mi][1] = uf(AsL[rb + 160]);
                ah[mi][2] = uf(AsH[rb + 4]);   al[mi][2] = uf(AsL[rb + 4]);
                ah[mi][3] = uf(AsH[rb + 164]); al[mi][3] = uf(AsL[rb + 164]);
            }
#pragma unroll
            for (int ni = 0; ni < 4; ni++) {
                int nb = (wn * 32 + ni * 8 + g) * 20 + ks * 8 + tg;
                bh[ni][0] = uf(WsH[nb]);     bl[ni][0] = uf(WsL[nb]);
                bh[ni][1] = uf(WsH[nb + 4]); bl[ni][1] = uf(WsL[nb + 4]);
            }
#pragma unroll
            for (int mi = 0; mi < 2; mi++)
#pragma unroll
                for (int ni = 0; ni < 4; ni++)
                    mma3(acc[mi][ni], ah[mi], al[mi], bh[ni], bl[ni]);
        }
    }
    __syncthreads();   // all stage reads done before zb overlay
#pragma unroll
    for (int mi = 0; mi < 2; mi++) {
#pragma unroll
        for (int ni = 0; ni < 4; ni++) {
            int row = wm * 32 + mi * 16 + g;
            int col = wn * 32 + ni * 8 + 2 * tg;
            zb[row][col]         = acc[mi][ni][0];
            zb[row][col + 1]     = acc[mi][ni][1];
            zb[row + 8][col]     = acc[mi][ni][2];
            zb[row + 8][col + 1] = acc[mi][ni][3];
        }
    }
    __syncthreads();
    for (int idx = tid; idx < 64 * 32; idx += 256) {
        int ml = idx >> 5, jj = idx & 31;
        int j = j0 + jj;
        int m = m0 + ml;
        int cid = cin[m * W_ + t_eff];
        const float* pr = &proj[(size_t)cid * 4 * Hc_];
        float zi = zb[ml][jj]      + pr[j];
        float zf = zb[ml][32 + jj] + pr[Hc_ + j];
        float zg = zb[ml][64 + jj] + pr[2 * Hc_ + j];
        float zo = zb[ml][96 + jj] + pr[3 * Hc_ + j];
        size_t off = (size_t)m * Hc_ + j;
        float c = cst[off];
        c = sigf(zf) * c + sigf(zi) * tanhf(zg);
        cst[off] = c;
        float hv = sigf(zo) * tanhf(c);
        split2(hv, hnH[off], hnL[off]);
    }
}

// ---------------- persistent word BiLSTM (x prefetched, single sync) -----------
#define WP_W    (2 * 32 * 516)          // 33024
#define WP_AST  (2 * 64 * 68)           // 8704 per stage
#define WP_ZB   (64 * 36)               // 2304
#define WP_XS   (64 * 40)               // 2560
#define WP_SMEM_FLOATS (WP_W + 2 * WP_AST + WP_ZB + WP_XS)
__device__ __forceinline__ void grid_bar_dir(int dir) {
    __syncthreads();
    if (threadIdx.x == 0) {
        __threadfence();
        int gen = g_bar_gen[dir];
        if (atomicAdd((int*)&g_bar_count[dir], 1) == 63) {
            g_bar_count[dir] = 0;
            __threadfence();
            g_bar_gen[dir] = gen + 1;
        } else {
            while (g_bar_gen[dir] == gen) __nanosleep(20);
            __threadfence();
        }
    }
    __syncthreads();
}

__global__ void __launch_bounds__(256)
word_persistent(const float* __restrict__ WhhF, const float* __restrict__ WhhB)
{
    extern __shared__ float sm[];
    float* WH = sm;                       // 32 x 516
    float* WL = sm + 32 * 516;
    float* zbf = sm + WP_W + 2 * WP_AST;
    float (*zb)[36] = (float(*)[36])zbf;
    float* xs = zbf + WP_ZB;              // 64 x 40
    const uint32_t sbase = (uint32_t)__cvta_generic_to_shared(sm);
    const uint32_t xs_sa = sbase + (uint32_t)(WP_W + 2 * WP_AST + WP_ZB) * 4;

    const int dir = blockIdx.x >> 6;
    const int jb = blockIdx.x & 63;
    const int j0 = jb * 8;
    const int tid = threadIdx.x;
    const int w = tid >> 5, l = tid & 31;
    const int wm = w & 3, wn = w >> 2;
    const int g = l >> 2, tg = l & 3;

    const float* Whh = dir ? WhhB : WhhF;
    for (int i = tid; i < 32 * 512; i += 256) {
        int rr = i >> 9, k = i & 511;
        int wr = (rr >> 3) * Hw_ + j0 + (rr & 7);
        split2(Whh[(size_t)wr * Hw_ + k], WH[rr * 516 + k], WL[rr * 516 + k]);
    }
    __syncthreads();

    const float* xbase = g_wxproj[dir];
    float* cst = g_word_c[dir];

    for (int t = 0; t < S_; t++) {
        const int s = dir ? (S_ - 1 - t) : t;
        const float* hpH = g_wh_hi[dir][t & 1];
        const float* hpL = g_wh_lo[dir][t & 1];
        float* hnH = g_wh_hi[dir][(t + 1) & 1];
        float* hnL = g_wh_lo[dir][(t + 1) & 1];

        auto issueA = [&](int ko, int stage) {
            uint32_t sa = sbase + (uint32_t)(WP_W + stage * WP_AST) * 4;
#pragma unroll
            for (int q = 0; q < 4; q++) {
                int idx = tid + q * 256;
                int row = idx >> 4, col = (idx & 15) * 4;
                size_t goff = (size_t)row * Hw_ + ko * 64 + col;
                int soff = row * 68 + col;
                cpa16(sa + soff * 4, &hpH[goff]);
                cpa16(sa + (4352 + soff) * 4, &hpL[goff]);
            }
        };

        // group 0: A(0) + this step's x tile
        issueA(0, 0);
#pragma unroll
        for (int q = 0; q < 2; q++) {
            int e = tid * 2 + q;          // 0..511
            int b = e >> 3, sub = e & 7;
            int gate = sub >> 1, half = sub & 1;
            const float* gp = xbase + ((size_t)s * B_ + b) * 4 * Hw_ + gate * Hw_ + j0 + half * 4;
            cpa16(xs_sa + (b * 40 + gate * 8 + half * 4) * 4, gp);
        }
        cpa_commit();

        float acc[2][4] = {};
#pragma unroll 1
        for (int ko = 0; ko < 8; ko++) {
            cpa_wait0();
            __syncthreads();
            if (ko + 1 < 8) { issueA(ko + 1, (ko + 1) & 1); cpa_commit(); }
            const float* AH = sm + WP_W + (ko & 1) * WP_AST;
            const float* AL = AH + 4352;
#pragma unroll
            for (int k8 = 0; k8 < 8; k8++) {
                int kc = k8 * 8;
                unsigned ah[4], al[4];
                int rb = (wm * 16 + g) * 68 + kc + tg;
                ah[0] = uf(AH[rb]);              al[0] = uf(AL[rb]);
                ah[1] = uf(AH[rb + 8 * 68]);     al[1] = uf(AL[rb + 8 * 68]);
                ah[2] = uf(AH[rb + 4]);          al[2] = uf(AL[rb + 4]);
                ah[3] = uf(AH[rb + 8 * 68 + 4]); al[3] = uf(AL[rb + 8 * 68 + 4]);
#pragma unroll
                for (int ni = 0; ni < 2; ni++) {
                    int nb = (wn * 16 + ni * 8 + g) * 516 + ko * 64 + kc + tg;
                    unsigned bh[2], bl[2];
                    bh[0] = uf(WH[nb]);     bl[0] = uf(WL[nb]);
                    bh[1] = uf(WH[nb + 4]); bl[1] = uf(WL[nb + 4]);
                    mma3(acc[ni], ah, al, bh, bl);
                }
            }
        }
#pragma unroll
        for (int ni = 0; ni < 2; ni++) {
            int row = wm * 16 + g;
            int col = wn * 16 + ni * 8 + 2 * tg;
            zb[row][col]         = acc[ni][0];
            zb[row][col + 1]     = acc[ni][1];
            zb[row + 8][col]     = acc[ni][2];
            zb[row + 8][col + 1] = acc[ni][3];
        }
        __syncthreads();
        for (int idx = tid; idx < 512; idx += 256) {
            int b = idx >> 3, jj = idx & 7;
            int j = j0 + jj;
            const float* xr = xs + b * 40;
            float zi = zb[b][jj]      + xr[jj];
            float zf = zb[b][8 + jj]  + xr[8 + jj];
            float zg = zb[b][16 + jj] + xr[16 + jj];
            float zo = zb[b][24 + jj] + xr[24 + jj];
            size_t off = (size_t)b * Hw_ + j;
            float c = cst[off];
            c = sigf(zf) * c + sigf(zi) * tanhf(zg);
            cst[off] = c;
            float hv = sigf(zo) * tanhf(c);
            float hh, hl;
            split2(hv, hh, hl);
            hnH[off] = hh; hnL[off] = hl;
            size_t eoff = ((size_t)s * B_ + b) * (2 * Hw_) + dir * Hw_ + j;
            g_enc_hi[eoff] = hh; g_enc_lo[eoff] = hl;
        }
        grid_bar_dir(dir);
    }
}

// ---------------- merged CRF forward + Viterbi (independent DPs) ----------------
__global__ void __launch_bounds__(32)
crf_fwd_kernel(const float* __restrict__ trans, const float* __restrict__ start,
               const float* __restrict__ endv, float* __restrict__ out, int out_size)
{
    __shared__ float tr[T_][T_];
    __shared__ float vec[T_];
    __shared__ unsigned char bp[S_ - 1][T_];
    const int to = threadIdx.x;
    for (int i = to; i < T_ * T_; i += T_) tr[i / T_][i % T_] = trans[i];

    if (blockIdx.x < B_) {
        // ----- CRF alpha -----
        const int b = blockIdx.x;
        vec[to] = start[to] + g_logits[(size_t)(0 * B_ + b) * T_ + to];
        __syncthreads();
        for (int s = 1; s < S_; s++) {
            float m = -1e30f;
#pragma unroll
            for (int f = 0; f < T_; f++) m = fmaxf(m, vec[f] + tr[f][to]);
            float sum = 0.0f;
#pragma unroll
            for (int f = 0; f < T_; f++) sum += expf(vec[f] + tr[f][to] - m);
            float a = m + logf(sum) + g_logits[((size_t)s * B_ + b) * T_ + to];
            __syncthreads();
            vec[to] = a;
            __syncthreads();
        }
        float v = vec[to] + endv[to];
        float m = v;
#pragma unroll
        for (int o = 16; o > 0; o >>= 1) m = fmaxf(m, __shfl_xor_sync(0xffffffffu, m, o));
        float e = expf(v - m);
#pragma unroll
        for (int o = 16; o > 0; o >>= 1) e += __shfl_xor_sync(0xffffffffu, e, o);
        if (to == 0) g_logZ[b] = m + logf(e);
    } else {
        // ----- Viterbi -----
        const int b = blockIdx.x - B_;
        vec[to] = start[to] + g_logits[(size_t)b * T_ + to];
        __syncthreads();
        for (int s = 1; s < S_; s++) {
            float best = -1e30f;
            int arg = 0;
#pragma unroll
            for (int f = 0; f < T_; f++) {
                float sc = vec[f] + tr[f][to];
                if (sc > best) { best = sc; arg = f; }
            }
            bp[s - 1][to] = (unsigned char)arg;
            float nv = best + g_logits[((size_t)s * B_ + b) * T_ + to];
            __syncthreads();
            vec[to] = nv;
            __syncthreads();
        }
        if (to == 0) {
            float best = -1e30f;
            int last = 0;
            for (int f = 0; f < T_; f++) {
                float sc = vec[f] + endv[f];
                if (sc > best) { best = sc; last = f; }
            }
            int tag = last;
            int base = 1 + b * S_;
            if (base + S_ - 1 < out_size) out[base + S_ - 1] = (float)tag;
            for (int s = S_ - 2; s >= 0; s--) {
                tag = bp[s][tag];
                if (base + s < out_size) out[base + s] = (float)tag;
            }
        }
    }
}

// ---------------- CRF gold score + loss ----------------
__global__ void __launch_bounds__(64)
crf_loss_kernel(const int* __restrict__ tags, const float* __restrict__ trans,
                const float* __restrict__ start, const float* __restrict__ endv,
                float* __restrict__ out, int out_size)
{
    __shared__ float red[B_];
    const int b = threadIdx.x;
    int prev = tags[0 * B_ + b];
    float score = start[prev];
    for (int s = 0; s < S_; s++) {
        int tg = tags[s * B_ + b];
        score += g_logits[((size_t)s * B_ + b) * T_ + tg];
        if (s > 0) score += trans[prev * T_ + tg];
        prev = tg;
    }
    score += endv[prev];
    red[b] = g_logZ[b] - score;
    __syncthreads();
    if (b == 0) {
        float t = 0.0f;
        for (int i = 0; i < B_; i++) t += red[i];
        if (out_size > 0) out[0] = t;
    }
}

// ---------------- host-side orchestration ----------------
extern "C" void kernel_launch(void* const* d_in, const int* in_sizes, int n_in,
                              void* d_out, int out_size) {
    (void)in_sizes; (void)n_in;
    const int*   word_inputs = (const int*)d_in[0];
    const int*   char_inputs = (const int*)d_in[1];
    const int*   cap_inputs  = (const int*)d_in[2];
    const int*   tag_inputs  = (const int*)d_in[3];
    const float* word_emb    = (const float*)d_in[4];
    const float* cap_emb     = (const float*)d_in[5];
    const float* char_emb    = (const float*)d_in[6];
    const float* cWih_f = (const float*)d_in[7];
    const float* cWhh_f = (const float*)d_in[8];
    const float* cbih_f = (const float*)d_in[9];
    const float* cbhh_f = (const float*)d_in[10];
    const float* cWih_b = (const float*)d_in[11];
    const float* cWhh_b = (const float*)d_in[12];
    const float* cbih_b = (const float*)d_in[13];
    const float* cbhh_b = (const float*)d_in[14];
    const float* wWih_f = (const float*)d_in[15];
    const float* wWhh_f = (const float*)d_in[16];
    const float* wbih_f = (const float*)d_in[17];
    const float* wbhh_f = (const float*)d_in[18];
    const float* wWih_b = (const float*)d_in[19];
    const float* wWhh_b = (const float*)d_in[20];
    const float* wbih_b = (const float*)d_in[21];
    const float* wbhh_b = (const float*)d_in[22];
    const float* ff1_W  = (const float*)d_in[23];
    const float* ff1_b  = (const float*)d_in[24];
    const float* ff2_W  = (const float*)d_in[25];
    const float* ff2_b  = (const float*)d_in[26];
    const float* trans  = (const float*)d_in[27];
    const float* start_trans = (const float*)d_in[28];
    const float* end_trans   = (const float*)d_in[29];
    float* out = (float*)d_out;

    float *pxh, *pxl, *pwih_h, *pwih_l, *pwx, *pench, *pencl, *ph1h, *ph1l, *plog;
    float *pff1h, *pff1l, *pff2h, *pff2l;
    cudaGetSymbolAddress((void**)&pxh,     g_x_hi);
    cudaGetSymbolAddress((void**)&pxl,     g_x_lo);
    cudaGetSymbolAddress((void**)&pwih_h,  g_wih_hi);
    cudaGetSymbolAddress((void**)&pwih_l,  g_wih_lo);
    cudaGetSymbolAddress((void**)&pwx,     g_wxproj);
    cudaGetSymbolAddress((void**)&pench,   g_enc_hi);
    cudaGetSymbolAddress((void**)&pencl,   g_enc_lo);
    cudaGetSymbolAddress((void**)&ph1h,    g_h1_hi);
    cudaGetSymbolAddress((void**)&ph1l,    g_h1_lo);
    cudaGetSymbolAddress((void**)&plog,    g_logits);
    cudaGetSymbolAddress((void**)&pff1h,   g_ff1w_hi);
    cudaGetSymbolAddress((void**)&pff1l,   g_ff1w_lo);
    cudaGetSymbolAddress((void**)&pff2h,   g_ff2w_hi);
    cudaGetSymbolAddress((void**)&pff2l,   g_ff2w_lo);

    const size_t wih_per = (size_t)4 * Hw_ * Kp_;
    const size_t wx_per = (size_t)NC_ * 4 * Hw_;

    const int ge_smem = 2 * GE_STAGE * (int)sizeof(float);   // 80 KB
    const int ch_smem = 2 * CH_STAGE * (int)sizeof(float);   // 60 KB
    const int wp_smem = WP_SMEM_FLOATS * (int)sizeof(float); // ~216 KB
    cudaFuncSetAttribute(mma_gemm_split, cudaFuncAttributeMaxDynamicSharedMemorySize, ge_smem);
    cudaFuncSetAttribute(char_step_kernel, cudaFuncAttributeMaxDynamicSharedMemorySize, ch_smem);
    cudaFuncSetAttribute(word_persistent, cudaFuncAttributeMaxDynamicSharedMemorySize, wp_smem);

    // 0) merged prep (launch 1) + vocab proj (launch 2)
    prep_kernel<<<2048, 256>>>(out, out_size, wWih_f, wWih_b, cWhh_f, cWhh_b, ff1_W, ff2_W);
    char_vocab_proj<<<2 * VC_, 256>>>(char_emb, cWih_f, cbih_f, cbhh_f, cWih_b, cbih_b, cbhh_b);

    // 1) char BiLSTM (launches 3..18 — ncu -s 5 captures a char_step)
    for (int t = 0; t < W_; t++)
        char_step_kernel<<<dim3(4, NC_ / 64, 2), 256, ch_smem>>>(char_inputs, t);

    // 2) build padded + split word input
    build_x_kernel<<<(NC_ * Kp_ + 255) / 256, 256>>>(word_inputs, cap_inputs, word_emb, cap_emb);

    // 3) word input projections
    mma_gemm_split<<<dim3(4 * Hw_ / 128, NC_ / 128), 256, ge_smem>>>(
        pxh, pxl, pwih_h, pwih_l, wbih_f, wbhh_f, pwx, nullptr, NC_, 4 * Hw_, Kp_, 0);
    mma_gemm_split<<<dim3(4 * Hw_ / 128, NC_ / 128), 256, ge_smem>>>(
        pxh, pxl, pwih_h + wih_per, pwih_l + wih_per, wbih_b, wbhh_b,
        pwx + wx_per, nullptr, NC_, 4 * Hw_, Kp_, 0);

    // 4) persistent word BiLSTM
    word_persistent<<<128, 256, wp_smem>>>(wWhh_f, wWhh_b);

    // 5) feed-forward head
    mma_gemm_split<<<dim3(Hw_ / 128, NC_ / 128), 256, ge_smem>>>(
        pench, pencl, pff1h, pff1l, ff1_b, nullptr, ph1h, ph1l, NC_, Hw_, 2 * Hw_, 1);
    mma_gemm_split<<<dim3(1, NC_ / 128), 256, ge_smem>>>(
        ph1h, ph1l, pff2h, pff2l, ff2_b, nullptr, plog, nullptr, NC_, T_, Hw_, 0);

    // 6) CRF forward + Viterbi (merged), then loss
    crf_fwd_kernel<<<2 * B_, T_>>>(trans, start_trans, end_trans, out, out_size);
    crf_loss_kernel<<<1, B_>>>(tag_inputs, trans, start_trans, end_trans, out, out_size);
}

// round 8
// speedup vs baseline: 2.5961x; 1.0297x over previous
#include <cuda_runtime.h>
#include <stdint.h>
#include <math.h>

// ---------------- problem constants ----------------
#define S_   256
#define B_   64
#define W_   16
#define Ec_  64
#define Hc_  128
#define E_   300
#define Hw_  512
#define T_   32
#define D_   557           // 1 + E + 2*Hc
#define Kp_  576           // D padded to multiple of 16
#define NC_  (B_ * S_)     // 16384 words for char encoder
#define VC_  128           // char vocab

// ---------------- scratch: interleaved (hi,lo) pairs for all MMA operands -------
__device__ float g_ch_int[2][2][NC_ * Hc_ * 2];      // char h pairs [dir][buf]
__device__ float g_char_c[2][NC_ * Hc_];
__device__ float g_cproj[2][VC_ * 4 * Hc_];          // per-vocab emb@Wih^T + biases
__device__ float g_cwhh_int[2][4 * Hc_ * Hc_ * 2];
__device__ float g_x_int[(size_t)NC_ * Kp_ * 2];
__device__ float g_wih_int[2][4 * Hw_ * Kp_ * 2];
__device__ float g_wxproj[2][(size_t)NC_ * 4 * Hw_]; // plain fp32
__device__ float g_wh_int[2][2][B_ * Hw_ * 2];
__device__ float g_word_c[2][B_ * Hw_];
__device__ float g_enc_int[(size_t)NC_ * 2 * Hw_ * 2];
__device__ float g_h1_int[(size_t)NC_ * Hw_ * 2];
__device__ float g_ff1w_int[Hw_ * 2 * Hw_ * 2];
__device__ float g_ff2w_int[T_ * Hw_ * 2];
__device__ float g_logits[NC_ * T_];
__device__ float g_logZ[B_];
__device__ volatile int g_bar_count[2];
__device__ volatile int g_bar_gen[2];

__device__ __forceinline__ float sigf(float x) { return 1.0f / (1.0f + expf(-x)); }

__device__ __forceinline__ unsigned f2tf(float f) {
    unsigned u;
    asm("cvt.rna.tf32.f32 %0, %1;" : "=r"(u) : "f"(f));
    return u;
}
__device__ __forceinline__ float fu(unsigned u) { return __uint_as_float(u); }
__device__ __forceinline__ unsigned uf(float f) { return __float_as_uint(f); }
__device__ __forceinline__ void split2(float v, float& hi, float& lo) {
    unsigned h = f2tf(v);
    hi = fu(h);
    lo = fu(f2tf(v - fu(h)));
}

__device__ __forceinline__ void mma8(float* c, const unsigned* a, const unsigned* b) {
    asm volatile(
        "mma.sync.aligned.m16n8k8.row.col.f32.tf32.tf32.f32 "
        "{%0,%1,%2,%3}, {%4,%5,%6,%7}, {%8,%9}, {%0,%1,%2,%3};"
        : "+f"(c[0]), "+f"(c[1]), "+f"(c[2]), "+f"(c[3])
        : "r"(a[0]), "r"(a[1]), "r"(a[2]), "r"(a[3]), "r"(b[0]), "r"(b[1]));
}
__device__ __forceinline__ void mma3(float* c, const unsigned* ah, const unsigned* al,
                                     const unsigned* bh, const unsigned* bl) {
    mma8(c, al, bh);
    mma8(c, ah, bl);
    mma8(c, ah, bh);
}

// cp.async helpers
__device__ __forceinline__ void cpa16(uint32_t saddr, const void* gptr) {
    asm volatile("cp.async.ca.shared.global [%0], [%1], 16;" :: "r"(saddr), "l"(gptr));
}
__device__ __forceinline__ void cpa_commit() {
    asm volatile("cp.async.commit_group;");
}
__device__ __forceinline__ void cpa_wait0() {
    asm volatile("cp.async.wait_group 0;");
}

// ---------------- merged prep kernel ----------------
__global__ void __launch_bounds__(256)
prep_kernel(float* __restrict__ out, int out_size,
            const float* __restrict__ wWf, const float* __restrict__ wWb,
            const float* __restrict__ cWhhF, const float* __restrict__ cWhhB,
            const float* __restrict__ ff1W, const float* __restrict__ ff2W)
{
    const int stride = gridDim.x * blockDim.x;
    const int i0 = blockIdx.x * blockDim.x + threadIdx.x;
    for (int i = i0; i < out_size; i += stride) out[i] = 0.0f;
    for (size_t i = i0; i < (size_t)2 * 2 * NC_ * Hc_ * 2; i += stride)
        (&g_ch_int[0][0][0])[i] = 0.0f;
    for (int i = i0; i < 2 * NC_ * Hc_; i += stride)
        (&g_char_c[0][0])[i] = 0.0f;
    for (int i = i0; i < 2 * 2 * B_ * Hw_ * 2; i += stride)
        (&g_wh_int[0][0][0])[i] = 0.0f;
    for (int i = i0; i < 2 * B_ * Hw_; i += stride)
        (&g_word_c[0][0])[i] = 0.0f;
    // pad + split-interleave word Wih
    const int per = 4 * Hw_ * Kp_;
    for (int idx = i0; idx < 2 * per; idx += stride) {
        int dir = idx / per;
        int r = idx - dir * per;
        int n = r / Kp_, k = r - n * Kp_;
        const float* Wsrc = dir ? wWb : wWf;
        float v = (k < D_) ? Wsrc[(size_t)n * D_ + k] : 0.0f;
        split2(v, g_wih_int[dir][r * 2], g_wih_int[dir][r * 2 + 1]);
    }
    const int cn = 4 * Hc_ * Hc_;
    for (int i = i0; i < cn; i += stride) {
        split2(cWhhF[i], g_cwhh_int[0][i * 2], g_cwhh_int[0][i * 2 + 1]);
        split2(cWhhB[i], g_cwhh_int[1][i * 2], g_cwhh_int[1][i * 2 + 1]);
    }
    for (int i = i0; i < Hw_ * 2 * Hw_; i += stride)
        split2(ff1W[i], g_ff1w_int[i * 2], g_ff1w_int[i * 2 + 1]);
    for (int i = i0; i < T_ * Hw_; i += stride)
        split2(ff2W[i], g_ff2w_int[i * 2], g_ff2w_int[i * 2 + 1]);
}

__global__ void __launch_bounds__(256)
char_vocab_proj(const float* __restrict__ emb,
                const float* __restrict__ WihF, const float* __restrict__ bihF,
                const float* __restrict__ bhhF,
                const float* __restrict__ WihB, const float* __restrict__ bihB,
                const float* __restrict__ bhhB)
{
    int dir = blockIdx.x >> 7;
    int cid = blockIdx.x & 127;
    const float* Wih = dir ? WihB : WihF;
    const float* bih = dir ? bihB : bihF;
    const float* bhh = dir ? bhhB : bhhF;
    __shared__ float e[Ec_];
    if (threadIdx.x < Ec_) e[threadIdx.x] = emb[cid * Ec_ + threadIdx.x];
    __syncthreads();
    for (int n = threadIdx.x; n < 4 * Hc_; n += 256) {
        float s = bih[n] + bhh[n];
        const float* wr = &Wih[(size_t)n * Ec_];
#pragma unroll 8
        for (int k = 0; k < Ec_; k++) s += e[k] * wr[k];
        g_cproj[dir][cid * 4 * Hc_ + n] = s;
    }
}

__global__ void __launch_bounds__(256)
build_x_kernel(const int* __restrict__ wid, const int* __restrict__ cap,
               const float* __restrict__ wemb, const float* __restrict__ cemb)
{
    int idx = blockIdx.x * blockDim.x + threadIdx.x;
    if (idx >= NC_ * Kp_) return;
    int d = idx % Kp_;
    int sb = idx / Kp_;
    int s = sb / B_, b = sb % B_;
    float v = 0.0f;
    if (d < E_) {
        v = wemb[(size_t)wid[s * B_ + b] * E_ + d];
    } else if (d < E_ + 2 * Hc_) {
        int j = d - E_;
        int n = b * S_ + s;
        size_t off = (j < Hc_) ? ((size_t)n * Hc_ + j) : ((size_t)n * Hc_ + (j - Hc_));
        int dd = (j < Hc_) ? 0 : 1;
        v = g_ch_int[dd][0][off * 2] + g_ch_int[dd][0][off * 2 + 1];
    } else if (d == E_ + 2 * Hc_) {
        v = cemb[cap[s * B_ + b]];
    }
    split2(v, g_x_int[(size_t)idx * 2], g_x_int[(size_t)idx * 2 + 1]);
}

// ---------------- interleaved 3xTF32 GEMM (cp.async, single sync / k-tile) -----
// C = act(A @ W^T + b1 + b2). Aint/Wint: (hi,lo) pairs, logical (M,K)/(N,K).
// Tile 128x128x16. Stage: As 128x40 + Ws 128x40 = 10240 floats = 40KB; 2 stages.
#define GE_STAGE 10240
__global__ void __launch_bounds__(256, 2)
mma_gemm_int(const float* __restrict__ Aint, const float* __restrict__ Wint,
             const float* __restrict__ b1, const float* __restrict__ b2,
             float* __restrict__ C, int out_int,
             int M, int N, int K, int act)
{
    extern __shared__ __align__(16) float sm[];
    const int tid = threadIdx.x;
    const int w = tid >> 5, l = tid & 31;
    const int wm = w & 1, wn = w >> 1;
    const int g = l >> 2, tg = l & 3;
    const int m0 = blockIdx.y * 128, n0 = blockIdx.x * 128;
    const int r8 = tid >> 3, c8 = tid & 7;   // 32 rows x 8 chunks per pass
    const uint32_t sbase = (uint32_t)__cvta_generic_to_shared(sm);

    float acc[4][4][4] = {};
    const int KT = K >> 4;

    auto issue = [&](int kk, int stage) {
        uint32_t sa = sbase + (uint32_t)(stage * GE_STAGE) * 4;
#pragma unroll
        for (int h = 0; h < 4; h++) {
            int rr = r8 + h * 32;
            size_t aoff = ((size_t)(m0 + rr) * K + kk * 16) * 2 + c8 * 4;
            cpa16(sa + (rr * 40 + c8 * 4) * 4, &Aint[aoff]);
            int n = n0 + rr;
            if (n >= N) n = N - 1;   // clamp; clamped lanes never stored
            size_t woff = ((size_t)n * K + kk * 16) * 2 + c8 * 4;
            cpa16(sa + (5120 + rr * 40 + c8 * 4) * 4, &Wint[woff]);
        }
        cpa_commit();
    };

    issue(0, 0);
    for (int kk = 0; kk < KT; kk++) {
        cpa_wait0();
        __syncthreads();
        if (kk + 1 < KT) issue(kk + 1, (kk + 1) & 1);
        const float2* As2 = (const float2*)(sm + (kk & 1) * GE_STAGE);
        const float2* Ws2 = (const float2*)(sm + (kk & 1) * GE_STAGE + 5120);
#pragma unroll
        for (int ks = 0; ks < 2; ks++) {
            unsigned ah[4][4], al[4][4], bh[4][2], bl[4][2];
#pragma unroll
            for (int mi = 0; mi < 4; mi++) {
                int rbase = wm * 64 + mi * 16 + g;
                float2 v0 = As2[rbase * 20 + ks * 8 + tg];
                float2 v1 = As2[(rbase + 8) * 20 + ks * 8 + tg];
                float2 v2 = As2[rbase * 20 + ks * 8 + tg + 4];
                float2 v3 = As2[(rbase + 8) * 20 + ks * 8 + tg + 4];
                ah[mi][0] = uf(v0.x); al[mi][0] = uf(v0.y);
                ah[mi][1] = uf(v1.x); al[mi][1] = uf(v1.y);
                ah[mi][2] = uf(v2.x); al[mi][2] = uf(v2.y);
                ah[mi][3] = uf(v3.x); al[mi][3] = uf(v3.y);
            }
#pragma unroll
            for (int ni = 0; ni < 4; ni++) {
                int nb = wn * 32 + ni * 8 + g;
                float2 w0 = Ws2[nb * 20 + ks * 8 + tg];
                float2 w1 = Ws2[nb * 20 + ks * 8 + tg + 4];
                bh[ni][0] = uf(w0.x); bl[ni][0] = uf(w0.y);
                bh[ni][1] = uf(w1.x); bl[ni][1] = uf(w1.y);
            }
#pragma unroll
            for (int mi = 0; mi < 4; mi++)
#pragma unroll
                for (int ni = 0; ni < 4; ni++)
                    mma3(acc[mi][ni], ah[mi], al[mi], bh[ni], bl[ni]);
        }
    }
#pragma unroll
    for (int mi = 0; mi < 4; mi++) {
#pragma unroll
        for (int ni = 0; ni < 4; ni++) {
            int m = m0 + wm * 64 + mi * 16 + g;
            int n = n0 + wn * 32 + ni * 8 + 2 * tg;
#pragma unroll
            for (int q = 0; q < 4; q++) {
                int mm = m + (q >> 1) * 8;
                int nn = n + (q & 1);
                if (nn >= N) continue;
                float v = acc[mi][ni][q];
                if (b1) v += b1[nn];
                if (b2) v += b2[nn];
                if (act == 1) v = tanhf(v);
                size_t off = (size_t)mm * N + nn;
                if (out_int) split2(v, C[off * 2], C[off * 2 + 1]);
                else C[off] = v;
            }
        }
    }
}

// ---------------- fused char LSTM step: tile M=128, N=128, K=128 ----------------
// grid (4, 128, 2). Stage: A 128x40 + W 128x40 = 40KB; 2 stages = 80KB.
#define CH_STAGE 10240
__global__ void __launch_bounds__(256, 2)
char_step_kernel(const int* __restrict__ cin, int t)
{
    const int dir = blockIdx.z;
    const int t_eff = dir ? (W_ - 1 - t) : t;
    const float* hp = g_ch_int[dir][t & 1];
    float* hn = g_ch_int[dir][(t + 1) & 1];
    float* cst = g_char_c[dir];
    const float* WInt = g_cwhh_int[dir];
    const float* proj = g_cproj[dir];

    extern __shared__ __align__(16) float sm[];
    float (*zb)[132] = (float(*)[132])sm;
    const uint32_t sbase = (uint32_t)__cvta_generic_to_shared(sm);

    const int tid = threadIdx.x;
    const int w = tid >> 5, l = tid & 31;
    const int wm = w & 1, wn = w >> 1;
    const int g = l >> 2, tg = l & 3;
    const int j0 = blockIdx.x * 32;
    const int m0 = blockIdx.y * 128;
    const int r8 = tid >> 3, c8 = tid & 7;

    float acc[4][4][4] = {};

    auto issue = [&](int kk, int stage) {
        uint32_t sa = sbase + (uint32_t)(stage * CH_STAGE) * 4;
#pragma unroll
        for (int h = 0; h < 4; h++) {
            int rr = r8 + h * 32;
            size_t aoff = ((size_t)(m0 + rr) * Hc_ + kk * 16) * 2 + c8 * 4;
            cpa16(sa + (rr * 40 + c8 * 4) * 4, &hp[aoff]);
            int wr = (rr >> 5) * Hc_ + j0 + (rr & 31);
            size_t woff = ((size_t)wr * Hc_ + kk * 16) * 2 + c8 * 4;
            cpa16(sa + (5120 + rr * 40 + c8 * 4) * 4, &WInt[woff]);
        }
        cpa_commit();
    };

    issue(0, 0);
#pragma unroll 1
    for (int kk = 0; kk < 8; kk++) {
        cpa_wait0();
        __syncthreads();
        if (kk + 1 < 8) issue(kk + 1, (kk + 1) & 1);
        const float2* As2 = (const float2*)(sm + (kk & 1) * CH_STAGE);
        const float2* Ws2 = (const float2*)(sm + (kk & 1) * CH_STAGE + 5120);
#pragma unroll
        for (int ks = 0; ks < 2; ks++) {
            unsigned ah[4][4], al[4][4], bh[4][2], bl[4][2];
#pragma unroll
            for (int mi = 0; mi < 4; mi++) {
                int rbase = wm * 64 + mi * 16 + g;
                float2 v0 = As2[rbase * 20 + ks * 8 + tg];
                float2 v1 = As2[(rbase + 8) * 20 + ks * 8 + tg];
                float2 v2 = As2[rbase * 20 + ks * 8 + tg + 4];
                float2 v3 = As2[(rbase + 8) * 20 + ks * 8 + tg + 4];
                ah[mi][0] = uf(v0.x); al[mi][0] = uf(v0.y);
                ah[mi][1] = uf(v1.x); al[mi][1] = uf(v1.y);
                ah[mi][2] = uf(v2.x); al[mi][2] = uf(v2.y);
                ah[mi][3] = uf(v3.x); al[mi][3] = uf(v3.y);
            }
#pragma unroll
            for (int ni = 0; ni < 4; ni++) {
                int nb = wn * 32 + ni * 8 + g;
                float2 w0 = Ws2[nb * 20 + ks * 8 + tg];
                float2 w1 = Ws2[nb * 20 + ks * 8 + tg + 4];
                bh[ni][0] = uf(w0.x); bl[ni][0] = uf(w0.y);
                bh[ni][1] = uf(w1.x); bl[ni][1] = uf(w1.y);
            }
#pragma unroll
            for (int mi = 0; mi < 4; mi++)
#pragma unroll
                for (int ni = 0; ni < 4; ni++)
                    mma3(acc[mi][ni], ah[mi], al[mi], bh[ni], bl[ni]);
        }
    }
    __syncthreads();   // all stage reads done before zb overlay
#pragma unroll
    for (int mi = 0; mi < 4; mi++) {
#pragma unroll
        for (int ni = 0; ni < 4; ni++) {
            int row = wm * 64 + mi * 16 + g;
            int col = wn * 32 + ni * 8 + 2 * tg;
            zb[row][col]         = acc[mi][ni][0];
            zb[row][col + 1]     = acc[mi][ni][1];
            zb[row + 8][col]     = acc[mi][ni][2];
            zb[row + 8][col + 1] = acc[mi][ni][3];
        }
    }
    __syncthreads();
    for (int idx = tid; idx < 128 * 32; idx += 256) {
        int ml = idx >> 5, jj = idx & 31;
        int j = j0 + jj;
        int m = m0 + ml;
        int cid = cin[m * W_ + t_eff];
        const float* pr = &proj[(size_t)cid * 4 * Hc_];
        float zi = zb[ml][jj]      + pr[j];
        float zf = zb[ml][32 + jj] + pr[Hc_ + j];
        float zg = zb[ml][64 + jj] + pr[2 * Hc_ + j];
        float zo = zb[ml][96 + jj] + pr[3 * Hc_ + j];
        size_t off = (size_t)m * Hc_ + j;
        float c = cst[off];
        c = sigf(zf) * c + sigf(zi) * tanhf(zg);
        cst[off] = c;
        float hv = sigf(zo) * tanhf(c);
        split2(hv, hn[off * 2], hn[off * 2 + 1]);
    }
}

// ---------------- persistent word BiLSTM (interleaved, x prefetched) ------------
#define WP_W    (32 * 1032)             // 33024: 32 rows x 512k x2 + pad
#define WP_AST  (64 * 136)              // 8704 per stage
#define WP_ZB   (64 * 36)               // 2304
#define WP_XS   (64 * 40)               // 2560
#define WP_SMEM_FLOATS (WP_W + 2 * WP_AST + WP_ZB + WP_XS)
__device__ __forceinline__ void grid_bar_dir(int dir) {
    __syncthreads();
    if (threadIdx.x == 0) {
        __threadfence();
        int gen = g_bar_gen[dir];
        if (atomicAdd((int*)&g_bar_count[dir], 1) == 63) {
            g_bar_count[dir] = 0;
            __threadfence();
            g_bar_gen[dir] = gen + 1;
        } else {
            while (g_bar_gen[dir] == gen) __nanosleep(20);
            __threadfence();
        }
    }
    __syncthreads();
}

__global__ void __launch_bounds__(256)
word_persistent(const float* __restrict__ WhhF, const float* __restrict__ WhhB)
{
    extern __shared__ float sm[];
    float* WS = sm;                       // interleaved 32 x (512k x2 + 8 pad)
    float* zbf = sm + WP_W + 2 * WP_AST;
    float (*zb)[36] = (float(*)[36])zbf;
    float* xs = zbf + WP_ZB;              // 64 x 40, plain x tile
    const uint32_t sbase = (uint32_t)__cvta_generic_to_shared(sm);
    const uint32_t xs_sa = sbase + (uint32_t)(WP_W + 2 * WP_AST + WP_ZB) * 4;

    const int dir = blockIdx.x >> 6;
    const int jb = blockIdx.x & 63;
    const int j0 = jb * 8;
    const int tid = threadIdx.x;
    const int w = tid >> 5, l = tid & 31;
    const int wm = w & 3, wn = w >> 2;
    const int g = l >> 2, tg = l & 3;

    const float* Whh = dir ? WhhB : WhhF;
    for (int i = tid; i < 32 * 512; i += 256) {
        int rr = i >> 9, k = i & 511;
        int wr = (rr >> 3) * Hw_ + j0 + (rr & 7);
        split2(Whh[(size_t)wr * Hw_ + k], WS[rr * 1032 + 2 * k], WS[rr * 1032 + 2 * k + 1]);
    }
    __syncthreads();

    const float* xbase = g_wxproj[dir];
    float* cst = g_word_c[dir];
    const float2* W2 = (const float2*)WS;   // pitch 516 float2

    for (int t = 0; t < S_; t++) {
        const int s = dir ? (S_ - 1 - t) : t;
        const float* hp = g_wh_int[dir][t & 1];
        float* hn = g_wh_int[dir][(t + 1) & 1];

        auto issueA = [&](int ko, int stage) {
            uint32_t sa = sbase + (uint32_t)(WP_W + stage * WP_AST) * 4;
#pragma unroll
            for (int q = 0; q < 8; q++) {
                int e = tid + q * 256;
                int row = e >> 5, c = e & 31;   // 64 rows x 32 chunks
                size_t goff = ((size_t)row * Hw_ + ko * 64) * 2 + c * 4;
                cpa16(sa + (row * 136 + c * 4) * 4, &hp[goff]);
            }
        };

        // group 0: A(0) + this step's x tile
        issueA(0, 0);
#pragma unroll
        for (int q = 0; q < 2; q++) {
            int e = tid * 2 + q;          // 0..511
            int b = e >> 3, sub = e & 7;
            int gate = sub >> 1, half = sub & 1;
            const float* gp = xbase + ((size_t)s * B_ + b) * 4 * Hw_ + gate * Hw_ + j0 + half * 4;
            cpa16(xs_sa + (b * 40 + gate * 8 + half * 4) * 4, gp);
        }
        cpa_commit();

        float acc[2][4] = {};
#pragma unroll 1
        for (int ko = 0; ko < 8; ko++) {
            cpa_wait0();
            __syncthreads();
            if (ko + 1 < 8) { issueA(ko + 1, (ko + 1) & 1); cpa_commit(); }
            const float2* A2 = (const float2*)(sm + WP_W + (ko & 1) * WP_AST);  // pitch 68
#pragma unroll
            for (int k8 = 0; k8 < 8; k8++) {
                int kc = k8 * 8;
                unsigned ah[4], al[4];
                float2 v0 = A2[(wm * 16 + g) * 68 + kc + tg];
                float2 v1 = A2[(wm * 16 + g + 8) * 68 + kc + tg];
                float2 v2 = A2[(wm * 16 + g) * 68 + kc + tg + 4];
                float2 v3 = A2[(wm * 16 + g + 8) * 68 + kc + tg + 4];
                ah[0] = uf(v0.x); al[0] = uf(v0.y);
                ah[1] = uf(v1.x); al[1] = uf(v1.y);
                ah[2] = uf(v2.x); al[2] = uf(v2.y);
                ah[3] = uf(v3.x); al[3] = uf(v3.y);
#pragma unroll
                for (int ni = 0; ni < 2; ni++) {
                    int nb = wn * 16 + ni * 8 + g;
                    float2 w0 = W2[nb * 516 + ko * 64 + kc + tg];
                    float2 w1 = W2[nb * 516 + ko * 64 + kc + tg + 4];
                    unsigned bh[2], bl[2];
                    bh[0] = uf(w0.x); bl[0] = uf(w0.y);
                    bh[1] = uf(w1.x); bl[1] = uf(w1.y);
                    mma3(acc[ni], ah, al, bh, bl);
                }
            }
        }
#pragma unroll
        for (int ni = 0; ni < 2; ni++) {
            int row = wm * 16 + g;
            int col = wn * 16 + ni * 8 + 2 * tg;
            zb[row][col]         = acc[ni][0];
            zb[row][col + 1]     = acc[ni][1];
            zb[row + 8][col]     = acc[ni][2];
            zb[row + 8][col + 1] = acc[ni][3];
        }
        __syncthreads();
        for (int idx = tid; idx < 512; idx += 256) {
            int b = idx >> 3, jj = idx & 7;
            int j = j0 + jj;
            const float* xr = xs + b * 40;
            float zi = zb[b][jj]      + xr[jj];
            float zf = zb[b][8 + jj]  + xr[8 + jj];
            float zg = zb[b][16 + jj] + xr[16 + jj];
            float zo = zb[b][24 + jj] + xr[24 + jj];
            size_t off = (size_t)b * Hw_ + j;
            float c = cst[off];
            c = sigf(zf) * c + sigf(zi) * tanhf(zg);
            cst[off] = c;
            float hv = sigf(zo) * tanhf(c);
            float hh, hl;
            split2(hv, hh, hl);
            hn[off * 2] = hh; hn[off * 2 + 1] = hl;
            size_t eoff = ((size_t)s * B_ + b) * (2 * Hw_) + dir * Hw_ + j;
            g_enc_int[eoff * 2] = hh; g_enc_int[eoff * 2 + 1] = hl;
        }
        grid_bar_dir(dir);
    }
}

// ---------------- merged CRF forward + Viterbi ----------------
__global__ void __launch_bounds__(32)
crf_fwd_kernel(const float* __restrict__ trans, const float* __restrict__ start,
               const float* __restrict__ endv, float* __restrict__ out, int out_size)
{
    __shared__ float tr[T_][T_];
    __shared__ float vec[T_];
    __shared__ unsigned char bp[S_ - 1][T_];
    const int to = threadIdx.x;
    for (int i = to; i < T_ * T_; i += T_) tr[i / T_][i % T_] = trans[i];

    if (blockIdx.x < B_) {
        const int b = blockIdx.x;
        vec[to] = start[to] + g_logits[(size_t)(0 * B_ + b) * T_ + to];
        __syncthreads();
        for (int s = 1; s < S_; s++) {
            float m = -1e30f;
#pragma unroll
            for (int f = 0; f < T_; f++) m = fmaxf(m, vec[f] + tr[f][to]);
            float sum = 0.0f;
#pragma unroll
            for (int f = 0; f < T_; f++) sum += expf(vec[f] + tr[f][to] - m);
            float a = m + logf(sum) + g_logits[((size_t)s * B_ + b) * T_ + to];
            __syncthreads();
            vec[to] = a;
            __syncthreads();
        }
        float v = vec[to] + endv[to];
        float m = v;
#pragma unroll
        for (int o = 16; o > 0; o >>= 1) m = fmaxf(m, __shfl_xor_sync(0xffffffffu, m, o));
        float e = expf(v - m);
#pragma unroll
        for (int o = 16; o > 0; o >>= 1) e += __shfl_xor_sync(0xffffffffu, e, o);
        if (to == 0) g_logZ[b] = m + logf(e);
    } else {
        const int b = blockIdx.x - B_;
        vec[to] = start[to] + g_logits[(size_t)b * T_ + to];
        __syncthreads();
        for (int s = 1; s < S_; s++) {
            float best = -1e30f;
            int arg = 0;
#pragma unroll
            for (int f = 0; f < T_; f++) {
                float sc = vec[f] + tr[f][to];
                if (sc > best) { best = sc; arg = f; }
            }
            bp[s - 1][to] = (unsigned char)arg;
            float nv = best + g_logits[((size_t)s * B_ + b) * T_ + to];
            __syncthreads();
            vec[to] = nv;
            __syncthreads();
        }
        if (to == 0) {
            float best = -1e30f;
            int last = 0;
            for (int f = 0; f < T_; f++) {
                float sc = vec[f] + endv[f];
                if (sc > best) { best = sc; last = f; }
            }
            int tag = last;
            int base = 1 + b * S_;
            if (base + S_ - 1 < out_size) out[base + S_ - 1] = (float)tag;
            for (int s = S_ - 2; s >= 0; s--) {
                tag = bp[s][tag];
                if (base + s < out_size) out[base + s] = (float)tag;
            }
        }
    }
}

__global__ void __launch_bounds__(64)
crf_loss_kernel(const int* __restrict__ tags, const float* __restrict__ trans,
                const float* __restrict__ start, const float* __restrict__ endv,
                float* __restrict__ out, int out_size)
{
    __shared__ float red[B_];
    const int b = threadIdx.x;
    int prev = tags[0 * B_ + b];
    float score = start[prev];
    for (int s = 0; s < S_; s++) {
        int tg = tags[s * B_ + b];
        score += g_logits[((size_t)s * B_ + b) * T_ + tg];
        if (s > 0) score += trans[prev * T_ + tg];
        prev = tg;
    }
    score += endv[prev];
    red[b] = g_logZ[b] - score;
    __syncthreads();
    if (b == 0) {
        float t = 0.0f;
        for (int i = 0; i < B_; i++) t += red[i];
        if (out_size > 0) out[0] = t;
    }
}

// ---------------- host-side orchestration ----------------
extern "C" void kernel_launch(void* const* d_in, const int* in_sizes, int n_in,
                              void* d_out, int out_size) {
    (void)in_sizes; (void)n_in;
    const int*   word_inputs = (const int*)d_in[0];
    const int*   char_inputs = (const int*)d_in[1];
    const int*   cap_inputs  = (const int*)d_in[2];
    const int*   tag_inputs  = (const int*)d_in[3];
    const float* word_emb    = (const float*)d_in[4];
    const float* cap_emb     = (const float*)d_in[5];
    const float* char_emb    = (const float*)d_in[6];
    const float* cWih_f = (const float*)d_in[7];
    const float* cWhh_f = (const float*)d_in[8];
    const float* cbih_f = (const float*)d_in[9];
    const float* cbhh_f = (const float*)d_in[10];
    const float* cWih_b = (const float*)d_in[11];
    const float* cWhh_b = (const float*)d_in[12];
    const float* cbih_b = (const float*)d_in[13];
    const float* cbhh_b = (const float*)d_in[14];
    const float* wWih_f = (const float*)d_in[15];
    const float* wWhh_f = (const float*)d_in[16];
    const float* wbih_f = (const float*)d_in[17];
    const float* wbhh_f = (const float*)d_in[18];
    const float* wWih_b = (const float*)d_in[19];
    const float* wWhh_b = (const float*)d_in[20];
    const float* wbih_b = (const float*)d_in[21];
    const float* wbhh_b = (const float*)d_in[22];
    const float* ff1_W  = (const float*)d_in[23];
    const float* ff1_b  = (const float*)d_in[24];
    const float* ff2_W  = (const float*)d_in[25];
    const float* ff2_b  = (const float*)d_in[26];
    const float* trans  = (const float*)d_in[27];
    const float* start_trans = (const float*)d_in[28];
    const float* end_trans   = (const float*)d_in[29];
    float* out = (float*)d_out;

    float *pxi, *pwihi, *pwx, *penci, *ph1i, *plog, *pff1i, *pff2i;
    cudaGetSymbolAddress((void**)&pxi,   g_x_int);
    cudaGetSymbolAddress((void**)&pwihi, g_wih_int);
    cudaGetSymbolAddress((void**)&pwx,   g_wxproj);
    cudaGetSymbolAddress((void**)&penci, g_enc_int);
    cudaGetSymbolAddress((void**)&ph1i,  g_h1_int);
    cudaGetSymbolAddress((void**)&plog,  g_logits);
    cudaGetSymbolAddress((void**)&pff1i, g_ff1w_int);
    cudaGetSymbolAddress((void**)&pff2i, g_ff2w_int);

    const size_t wih_per = (size_t)4 * Hw_ * Kp_ * 2;
    const size_t wx_per = (size_t)NC_ * 4 * Hw_;

    const int ge_smem = 2 * GE_STAGE * (int)sizeof(float);   // 80 KB
    const int ch_smem = 2 * CH_STAGE * (int)sizeof(float);   // 80 KB
    const int wp_smem = WP_SMEM_FLOATS * (int)sizeof(float); // ~216 KB
    cudaFuncSetAttribute(mma_gemm_int, cudaFuncAttributeMaxDynamicSharedMemorySize, ge_smem);
    cudaFuncSetAttribute(char_step_kernel, cudaFuncAttributeMaxDynamicSharedMemorySize, ch_smem);
    cudaFuncSetAttribute(word_persistent, cudaFuncAttributeMaxDynamicSharedMemorySize, wp_smem);

    // 0) merged prep + vocab proj
    prep_kernel<<<2048, 256>>>(out, out_size, wWih_f, wWih_b, cWhh_f, cWhh_b, ff1_W, ff2_W);
    char_vocab_proj<<<2 * VC_, 256>>>(char_emb, cWih_f, cbih_f, cbhh_f, cWih_b, cbih_b, cbhh_b);

    // 1) char BiLSTM (launches 3..18 — ncu -s 5 captures a char_step)
    for (int t = 0; t < W_; t++)
        char_step_kernel<<<dim3(4, NC_ / 128, 2), 256, ch_smem>>>(char_inputs, t);

    // 2) build padded + split word input
    build_x_kernel<<<(NC_ * Kp_ + 255) / 256, 256>>>(word_inputs, cap_inputs, word_emb, cap_emb);

    // 3) word input projections (plain fp32 output)
    mma_gemm_int<<<dim3(4 * Hw_ / 128, NC_ / 128), 256, ge_smem>>>(
        pxi, pwihi, wbih_f, wbhh_f, pwx, 0, NC_, 4 * Hw_, Kp_, 0);
    mma_gemm_int<<<dim3(4 * Hw_ / 128, NC_ / 128), 256, ge_smem>>>(
        pxi, pwihi + wih_per, wbih_b, wbhh_b, pwx + wx_per, 0, NC_, 4 * Hw_, Kp_, 0);

    // 4) persistent word BiLSTM
    word_persistent<<<128, 256, wp_smem>>>(wWhh_f, wWhh_b);

    // 5) feed-forward head (ff1 -> interleaved h1; ff2 -> plain logits)
    mma_gemm_int<<<dim3(Hw_ / 128, NC_ / 128), 256, ge_smem>>>(
        penci, pff1i, ff1_b, nullptr, ph1i, 1, NC_, Hw_, 2 * Hw_, 1);
    mma_gemm_int<<<dim3(1, NC_ / 128), 256, ge_smem>>>(
        ph1i, pff2i, ff2_b, nullptr, plog, 0, NC_, T_, Hw_, 0);

    // 6) CRF forward + Viterbi, then loss
    crf_fwd_kernel<<<2 * B_, T_>>>(trans, start_trans, end_trans, out, out_size);
    crf_loss_kernel<<<1, B_>>>(tag_inputs, trans, start_trans, end_trans, out, out_size);
}